// round 12
// baseline (speedup 1.0000x reference)
#include <cuda_runtime.h>
#include <cuda_bf16.h>
#include <stdint.h>
#include <math.h>

#define NB 4
#define NL 2048
#define ND 1024
#define NH 16
#define NHD 64
#define NT (NB*NL)

// ---------------- scratch (device globals: no allocations allowed) ----------
__device__ __nv_bfloat16 g_xh[(size_t)NT*ND];
__device__ __nv_bfloat16 g_xl[(size_t)NT*ND];
__device__ __nv_bfloat16 g_wh[(size_t)4*ND*ND];   // Wq,Wk,Wv,Wo
__device__ __nv_bfloat16 g_wl[(size_t)4*ND*ND];
__device__ __nv_bfloat16 g_qh[(size_t)NB*NH*NL*NHD];  // [bh][l][hd]
__device__ __nv_bfloat16 g_ql[(size_t)NB*NH*NL*NHD];
__device__ __nv_bfloat16 g_kh[(size_t)NB*NH*NL*NHD];
__device__ __nv_bfloat16 g_kl[(size_t)NB*NH*NL*NHD];
__device__ __nv_bfloat16 g_vh[(size_t)NB*NH*NL*NHD];
__device__ __nv_bfloat16 g_vl[(size_t)NB*NH*NL*NHD];
__device__ __nv_bfloat16 g_ah[(size_t)NT*ND];     // attention out [t][h*64+hd]
__device__ __nv_bfloat16 g_al[(size_t)NT*ND];
__device__ float g_cos[NL*(NHD/2)];
__device__ float g_sin[NL*(NHD/2)];

// ---------------- helpers ----------------------------------------------------
__device__ __forceinline__ uint32_t smem_to_u32(const void* smem_ptr) {
    uint32_t addr;
    asm("{ .reg .u64 tmp; cvta.to.shared.u64 tmp, %1; cvt.u32.u64 %0, tmp; }"
        : "=r"(addr) : "l"(smem_ptr));
    return addr;
}
#define SWZ(off)   ((off) ^ (((off) >> 3) & 0x70))   // 128B rows
#define SWZ64(off) ((off) ^ (((off) >> 3) & 0x30))   // 64B rows

__device__ __forceinline__ void ldsm4(uint32_t* r, uint32_t a) {
    asm volatile("ldmatrix.sync.aligned.m8n8.x4.shared.b16 {%0,%1,%2,%3}, [%4];"
        : "=r"(r[0]), "=r"(r[1]), "=r"(r[2]), "=r"(r[3]) : "r"(a));
}
__device__ __forceinline__ void ldsm4t(uint32_t* r, uint32_t a) {
    asm volatile("ldmatrix.sync.aligned.m8n8.x4.trans.shared.b16 {%0,%1,%2,%3}, [%4];"
        : "=r"(r[0]), "=r"(r[1]), "=r"(r[2]), "=r"(r[3]) : "r"(a));
}
__device__ __forceinline__ void mma16816(float* c, const uint32_t* a,
                                         uint32_t b0, uint32_t b1) {
    asm volatile(
        "mma.sync.aligned.m16n8k16.row.col.f32.bf16.bf16.f32 "
        "{%0,%1,%2,%3}, {%4,%5,%6,%7}, {%8,%9}, {%0,%1,%2,%3};"
        : "+f"(c[0]), "+f"(c[1]), "+f"(c[2]), "+f"(c[3])
        : "r"(a[0]), "r"(a[1]), "r"(a[2]), "r"(a[3]), "r"(b0), "r"(b1));
}
__device__ __forceinline__ void split2(float a, float b, uint32_t& hi, uint32_t& lo) {
    __nv_bfloat162 h, l;
    h.x = __float2bfloat16(a); h.y = __float2bfloat16(b);
    l.x = __float2bfloat16(a - __bfloat162float(h.x));
    l.y = __float2bfloat16(b - __bfloat162float(h.y));
    hi = *(uint32_t*)&h; lo = *(uint32_t*)&l;
}
__device__ __forceinline__ void cp_async16(uint32_t sdst, const void* gsrc) {
    asm volatile("cp.async.cg.shared.global [%0], [%1], 16;"
        :: "r"(sdst), "l"(gsrc));
}
#define CP_COMMIT() asm volatile("cp.async.commit_group;" ::: "memory")
#define CP_WAIT(n)  asm volatile("cp.async.wait_group %0;" :: "n"(n) : "memory")

// [128 x 64] bf16 tile (row stride gstride elems) -> 128B-row swizzled smem
__device__ __forceinline__ void cp_tile(uint32_t sdst, const __nv_bfloat16* gsrc,
                                        int gstride, int tid) {
    #pragma unroll
    for (int it = 0; it < 4; it++) {
        int idx = tid + it * 256;          // 0..1023
        int row = idx >> 3, seg = idx & 7;
        cp_async16(sdst + SWZ((uint32_t)(row * 128 + seg * 16)),
                   gsrc + (size_t)row * gstride + seg * 8);
    }
}
// [128 x 32] bf16 tile -> 64B-row SW64 smem
__device__ __forceinline__ void cp_tile32(uint32_t sdst, const __nv_bfloat16* gsrc,
                                          int gstride, int tid) {
    #pragma unroll
    for (int it = 0; it < 2; it++) {
        int idx = tid + it * 256;          // 0..511
        int row = idx >> 2, seg = idx & 3;
        cp_async16(sdst + SWZ64((uint32_t)(row * 64 + seg * 16)),
                   gsrc + (size_t)row * gstride + seg * 8);
    }
}

// ---------------- K0a: RoPE tables (fp64 for accuracy) -----------------------
__global__ void rope_tables_kernel() {
    int idx = blockIdx.x * 256 + threadIdx.x;
    if (idx >= NL * (NHD/2)) return;
    int l = idx >> 5;
    int i = idx & 31;
    double inv = exp(-((double)(2*i) / (double)NHD) * log(10000.0));
    double a = (double)l * inv;
    g_cos[idx] = (float)cos(a);
    g_sin[idx] = (float)sin(a);
}

// ---------------- K0b: fp32 -> hi/lo bf16 converters -------------------------
__global__ void cvt_kernel(const float* __restrict__ src,
                           __nv_bfloat16* __restrict__ dh,
                           __nv_bfloat16* __restrict__ dl, int n4) {
    int i = blockIdx.x * 256 + threadIdx.x;
    if (i >= n4) return;
    float4 x = ((const float4*)src)[i];
    uint32_t h01, h23, l01, l23;
    split2(x.x, x.y, h01, l01);
    split2(x.z, x.w, h23, l23);
    ((uint2*)dh)[i] = make_uint2(h01, h23);
    ((uint2*)dl)[i] = make_uint2(l01, l23);
}
struct WPtrs { const float* p[4]; };
__global__ void cvt_w_kernel(WPtrs wp) {
    const int z = blockIdx.y;
    const float* src = wp.p[z];
    int i = blockIdx.x * 256 + threadIdx.x;
    if (i >= ND*ND/4) return;
    float4 x = ((const float4*)src)[i];
    uint32_t h01, h23, l01, l23;
    split2(x.x, x.y, h01, l01);
    split2(x.z, x.w, h23, l23);
    size_t base = (size_t)z * (ND*ND/4);
    ((uint2*)g_wh)[base + i] = make_uint2(h01, h23);
    ((uint2*)g_wl)[base + i] = make_uint2(l01, l23);
}

// ---------------- GEMM mainloop: K-chunk 32, 3-stage ring --------------------
// stage block 32KB: {AH:0, AL:8K, BH:16K, BL:24K}; stages at s%3 * 32768
#define GEMM_SMEM_BYTES (3*32768 + 1024)
#define NSTAGES_G (ND/32)      // 32

__device__ __forceinline__ void gemm_issue(
    uint32_t sb, int s, const __nv_bfloat16* Ah, const __nv_bfloat16* Al,
    const __nv_bfloat16* Bh, const __nv_bfloat16* Bl, int tid)
{
    uint32_t st = sb + (uint32_t)(s % 3) * 32768;
    int k0 = s * 32;
    cp_tile32(st + 0,     Ah + k0, ND, tid);
    cp_tile32(st + 8192,  Al + k0, ND, tid);
    cp_tile32(st + 16384, Bh + k0, ND, tid);
    cp_tile32(st + 24576, Bl + k0, ND, tid);
    CP_COMMIT();
}

__device__ __forceinline__ void gemm_mainloop_bf16(
    const __nv_bfloat16* __restrict__ Ah, const __nv_bfloat16* __restrict__ Al,
    const __nv_bfloat16* __restrict__ Bh, const __nv_bfloat16* __restrict__ Bl,
    uint32_t sb, float acc[2][8][4])
{
    const int tid = threadIdx.x;
    const int lid = tid & 31;
    const int wid = tid >> 5;
    const int wm = wid >> 1;
    const int wn = wid & 1;

    const int a_row = wm*32 + (lid & 7) + ((lid >> 3) & 1) * 8;
    const int a_cb  = (lid >> 4) * 8;
    const int b_row = wn*64 + (lid & 7) + ((lid >> 4) & 1) * 8;
    const int b_cb  = ((lid >> 3) & 1) * 8;

    gemm_issue(sb, 0, Ah, Al, Bh, Bl, tid);
    gemm_issue(sb, 1, Ah, Al, Bh, Bl, tid);
    for (int s = 0; s < NSTAGES_G; s++) {
        if (s + 2 < NSTAGES_G) { CP_WAIT(1); } else { CP_WAIT(0); }
        __syncthreads();     // reads of buffer (s+2)%3 (= stage s-1) retired
        if (s + 2 < NSTAGES_G)
            gemm_issue(sb, s + 2, Ah, Al, Bh, Bl, tid);
        uint32_t st = sb + (uint32_t)(s % 3) * 32768;

        #pragma unroll
        for (int ks = 0; ks < 2; ks++) {
            const int k0 = ks * 16;
            uint32_t ah[2][4], al[2][4], bh[4][4], bl[4][4];
            #pragma unroll
            for (int i = 0; i < 2; i++) {
                uint32_t sw = SWZ64((uint32_t)((a_row + i*16) * 64 + (k0 + a_cb) * 2));
                ldsm4(ah[i], st + 0 + sw);
                ldsm4(al[i], st + 8192 + sw);
            }
            #pragma unroll
            for (int jj = 0; jj < 4; jj++) {
                uint32_t sw = SWZ64((uint32_t)((b_row + jj*16) * 64 + (k0 + b_cb) * 2));
                ldsm4(bh[jj], st + 16384 + sw);
                ldsm4(bl[jj], st + 24576 + sw);
            }
            #pragma unroll
            for (int i = 0; i < 2; i++)
                #pragma unroll
                for (int jj = 0; jj < 4; jj++) {
                    mma16816(acc[i][2*jj],   ah[i], bh[jj][0], bh[jj][1]);
                    mma16816(acc[i][2*jj+1], ah[i], bh[jj][2], bh[jj][3]);
                    mma16816(acc[i][2*jj],   ah[i], bl[jj][0], bl[jj][1]);
                    mma16816(acc[i][2*jj+1], ah[i], bl[jj][2], bl[jj][3]);
                    mma16816(acc[i][2*jj],   al[i], bh[jj][0], bh[jj][1]);
                    mma16816(acc[i][2*jj+1], al[i], bh[jj][2], bh[jj][3]);
                }
        }
    }
}

// ---------------- K1: fused QKV projection + RoPE ----------------------------
__global__ void __launch_bounds__(256, 2)
qkv_mma_kernel(const float* __restrict__ bq, const float* __restrict__ bk,
               const float* __restrict__ bv)
{
    extern __shared__ char dsm[];
    char* sbase = (char*)((((uintptr_t)dsm) + 1023) & ~(uintptr_t)1023);
    uint32_t sb = smem_to_u32(sbase);
    const int tid = threadIdx.x;
    const int lid = tid & 31;
    const int wid = tid >> 5;
    const int wm = wid >> 1;
    const int wn = wid & 1;

    const int z = blockIdx.z;
    const float* bias = (z == 0) ? bq : (z == 1) ? bk : bv;
    __nv_bfloat16* dsth = (z == 0) ? g_qh : (z == 1) ? g_kh : g_vh;
    __nv_bfloat16* dstl = (z == 0) ? g_ql : (z == 1) ? g_kl : g_vl;

    const int mBase = blockIdx.y * 128;
    const int nBase = blockIdx.x * 128;

    float acc[2][8][4] = {};
    gemm_mainloop_bf16(g_xh + (size_t)mBase * ND, g_xl + (size_t)mBase * ND,
                       g_wh + (size_t)z * ND * ND + (size_t)nBase * ND,
                       g_wl + (size_t)z * ND * ND + (size_t)nBase * ND,
                       sb, acc);

    const int g  = lid >> 2;
    const int t4 = lid & 3;
    #pragma unroll
    for (int i = 0; i < 2; i++) {
        #pragma unroll
        for (int rr = 0; rr < 2; rr++) {
            int t = mBase + wm*32 + i*16 + g + rr*8;
            int b = t >> 11;
            int l = t & (NL - 1);
            #pragma unroll
            for (int j = 0; j < 8; j++) {
                int c = nBase + wn*64 + j*8 + 2*t4;
                float y0 = acc[i][j][rr*2+0] + bias[c];
                float y1 = acc[i][j][rr*2+1] + bias[c+1];
                if (z < 2) {
                    int p0 = (c & 63) >> 1;
                    float co = g_cos[l*32 + p0], si = g_sin[l*32 + p0];
                    float e = y0, o = y1;
                    y0 = e*co - o*si;
                    y1 = e*si + o*co;
                }
                int h  = c >> 6;
                int hd = c & 63;
                size_t idx = (((size_t)(b*NH + h))*NL + l)*NHD + hd;
                uint32_t hi, lo;
                split2(y0, y1, hi, lo);
                *(uint32_t*)&dsth[idx] = hi;
                *(uint32_t*)&dstl[idx] = lo;
            }
        }
    }
}

// ---------------- K3: output projection --------------------------------------
__global__ void __launch_bounds__(256, 2)
out_mma_kernel(const float* __restrict__ bias, float* __restrict__ out)
{
    extern __shared__ char dsm[];
    char* sbase = (char*)((((uintptr_t)dsm) + 1023) & ~(uintptr_t)1023);
    uint32_t sb = smem_to_u32(sbase);
    const int tid = threadIdx.x;
    const int lid = tid & 31;
    const int wid = tid >> 5;
    const int wm = wid >> 1;
    const int wn = wid & 1;

    const int mBase = blockIdx.y * 128;
    const int nBase = blockIdx.x * 128;

    float acc[2][8][4] = {};
    gemm_mainloop_bf16(g_ah + (size_t)mBase * ND, g_al + (size_t)mBase * ND,
                       g_wh + (size_t)3 * ND * ND + (size_t)nBase * ND,
                       g_wl + (size_t)3 * ND * ND + (size_t)nBase * ND,
                       sb, acc);

    const int g  = lid >> 2;
    const int t4 = lid & 3;
    #pragma unroll
    for (int i = 0; i < 2; i++) {
        #pragma unroll
        for (int rr = 0; rr < 2; rr++) {
            int t = mBase + wm*32 + i*16 + g + rr*8;
            #pragma unroll
            for (int j = 0; j < 8; j++) {
                int c = nBase + wn*64 + j*8 + 2*t4;
                *(float2*)&out[(size_t)t * ND + c] = make_float2(
                    acc[i][j][rr*2+0] + bias[c],
                    acc[i][j][rr*2+1] + bias[c+1]);
            }
        }
    }
}

// ======================= K2: flash attention (256 q-rows / CTA) ==============
// stage block 64KB: {KH:0, KL:16K, VH:32K, VL:48K}; stages at 0 / 65536
#define ATT_SMEM_BYTES (2*65536 + 1024)

__device__ __forceinline__ void attn_issue(uint32_t sb, int kt,
                                           const __nv_bfloat16* kh, const __nv_bfloat16* kl,
                                           const __nv_bfloat16* vh, const __nv_bfloat16* vl,
                                           int tid) {
    uint32_t st = sb + (uint32_t)(kt & 1) * 65536;
    size_t off = (size_t)kt * 128 * NHD;
    cp_tile(st + 0,     kh + off, NHD, tid);
    cp_tile(st + 16384, kl + off, NHD, tid);
    cp_tile(st + 32768, vh + off, NHD, tid);
    cp_tile(st + 49152, vl + off, NHD, tid);
    CP_COMMIT();
}

// grid (NL/256, NB*NH), 256 threads. CTA: 256 query rows of one (b,h).
// 8 warps; warp w owns rows [w*32, w*32+32) as two 16-row blocks.
__global__ void __launch_bounds__(256, 1) attn_mma_kernel() {
    extern __shared__ char dsm[];
    char* sbase = (char*)((((uintptr_t)dsm) + 1023) & ~(uintptr_t)1023);
    uint32_t sb = smem_to_u32(sbase);

    const int tid = threadIdx.x;
    const int lid = tid & 31;
    const int wid = tid >> 5;
    const int bh = blockIdx.y;
    const int qt = (int)gridDim.x - 1 - (int)blockIdx.x;   // heavy tiles first
    const int q0 = qt * 256;

    const size_t hoff = (size_t)bh * (NL*NHD);
    const __nv_bfloat16* qh = g_qh + hoff;
    const __nv_bfloat16* ql = g_ql + hoff;
    const __nv_bfloat16* kh = g_kh + hoff;
    const __nv_bfloat16* kl = g_kl + hoff;
    const __nv_bfloat16* vh = g_vh + hoff;
    const __nv_bfloat16* vl = g_vl + hoff;

    const int a_cb  = (lid >> 4) * 8;
    uint32_t Qh[2][4][4], Ql[2][4][4];

    // ---- stage the 256x64 Q tile through stage-0 K buffers in two passes ----
    #pragma unroll
    for (int p = 0; p < 2; p++) {
        cp_tile(sb + 0,     qh + (size_t)(q0 + p*128) * NHD, NHD, tid);
        cp_tile(sb + 16384, ql + (size_t)(q0 + p*128) * NHD, NHD, tid);
        CP_COMMIT();
        CP_WAIT(0);
        __syncthreads();
        if ((wid >> 2) == p) {
            int wloc = wid & 3;
            #pragma unroll
            for (int blk = 0; blk < 2; blk++) {
                int ar = wloc*32 + blk*16 + (lid & 7) + ((lid >> 3) & 1) * 8;
                #pragma unroll
                for (int kb = 0; kb < 4; kb++) {
                    uint32_t sw = SWZ((uint32_t)(ar * 128 + (kb*16 + a_cb) * 2));
                    ldsm4(Qh[blk][kb], sb + 0 + sw);
                    ldsm4(Ql[blk][kb], sb + 16384 + sw);
                }
            }
        }
        __syncthreads();
    }

    const int g  = lid >> 2;
    const int t4 = lid & 3;
    float mm[2][2], ll[2][2];
    #pragma unroll
    for (int blk = 0; blk < 2; blk++) {
        mm[blk][0] = -1e30f; mm[blk][1] = -1e30f;
        ll[blk][0] = 0.f;    ll[blk][1] = 0.f;
    }
    float O[2][8][4] = {};

    const int b_row = (lid & 7) + ((lid >> 4) & 1) * 8;
    const int b_cb  = ((lid >> 3) & 1) * 8;
    const int v_row = (lid & 7) + ((lid >> 3) & 1) * 8;
    const int v_col = ((lid >> 4) & 1) * 8;

    const int ktmax = (q0 + 255) >> 7;   // 2*qt+1

    attn_issue(sb, 0, kh, kl, vh, vl, tid);
    for (int kt = 0; kt <= ktmax; kt++) {
        CP_WAIT(0);
        __syncthreads();    // reads of buffer (kt-1)&1 retired; safe to refill
        if (kt + 1 <= ktmax)
            attn_issue(sb, kt + 1, kh, kl, vh, vl, tid);
        uint32_t st = sb + (uint32_t)(kt & 1) * 65536;

        #pragma unroll
        for (int blk = 0; blk < 2; blk++) {
            const int rbase = q0 + wid*32 + blk*16;   // rows rbase..rbase+15
            if (kt*128 > rbase + 15) continue;        // tile fully above diagonal
            const int qrow0 = rbase + g;

            // ---- S = Q K^T (3-term compensated) ----
            float sacc[16][4] = {};
            #pragma unroll
            for (int kb = 0; kb < 4; kb++) {
                #pragma unroll
                for (int jj = 0; jj < 8; jj++) {
                    uint32_t khf[4], klf[4];
                    uint32_t sw = SWZ((uint32_t)((jj*16 + b_row) * 128 + (kb*16 + b_cb) * 2));
                    ldsm4(khf, st + 0 + sw);
                    ldsm4(klf, st + 16384 + sw);
                    mma16816(sacc[2*jj],   Qh[blk][kb], khf[0], khf[1]);
                    mma16816(sacc[2*jj+1], Qh[blk][kb], khf[2], khf[3]);
                    mma16816(sacc[2*jj],   Ql[blk][kb], khf[0], khf[1]);
                    mma16816(sacc[2*jj+1], Ql[blk][kb], khf[2], khf[3]);
                    mma16816(sacc[2*jj],   Qh[blk][kb], klf[0], klf[1]);
                    mma16816(sacc[2*jj+1], Qh[blk][kb], klf[2], klf[3]);
                }
            }

            // ---- scale (+causal mask where the tile touches the diagonal) ----
            const float scale = 0.125f;
            if (kt*128 + 127 > qrow0) {
                #pragma unroll
                for (int j = 0; j < 16; j++) {
                    int col = kt*128 + j*8 + 2*t4;
                    #pragma unroll
                    for (int e = 0; e < 4; e++) {
                        int c = col + (e & 1);
                        int r = qrow0 + (e >> 1) * 8;
                        sacc[j][e] = (c > r) ? -1e30f : sacc[j][e] * scale;
                    }
                }
            } else {
                #pragma unroll
                for (int j = 0; j < 16; j++)
                    #pragma unroll
                    for (int e = 0; e < 4; e++) sacc[j][e] *= scale;
            }

            // ---- online softmax (quad-local reductions) ----
            float mx0 = -1e30f, mx1 = -1e30f;
            #pragma unroll
            for (int j = 0; j < 16; j++) {
                mx0 = fmaxf(mx0, fmaxf(sacc[j][0], sacc[j][1]));
                mx1 = fmaxf(mx1, fmaxf(sacc[j][2], sacc[j][3]));
            }
            mx0 = fmaxf(mx0, __shfl_xor_sync(0xffffffffu, mx0, 1));
            mx0 = fmaxf(mx0, __shfl_xor_sync(0xffffffffu, mx0, 2));
            mx1 = fmaxf(mx1, __shfl_xor_sync(0xffffffffu, mx1, 1));
            mx1 = fmaxf(mx1, __shfl_xor_sync(0xffffffffu, mx1, 2));

            float mn0 = fmaxf(mm[blk][0], mx0), mn1 = fmaxf(mm[blk][1], mx1);
            float al0 = __expf(mm[blk][0] - mn0), al1 = __expf(mm[blk][1] - mn1);
            mm[blk][0] = mn0; mm[blk][1] = mn1;

            float rs0 = 0.f, rs1 = 0.f;
            #pragma unroll
            for (int j = 0; j < 16; j++) {
                sacc[j][0] = __expf(sacc[j][0] - mn0);
                sacc[j][1] = __expf(sacc[j][1] - mn0);
                sacc[j][2] = __expf(sacc[j][2] - mn1);
                sacc[j][3] = __expf(sacc[j][3] - mn1);
                rs0 += sacc[j][0] + sacc[j][1];
                rs1 += sacc[j][2] + sacc[j][3];
            }
            rs0 += __shfl_xor_sync(0xffffffffu, rs0, 1);
            rs0 += __shfl_xor_sync(0xffffffffu, rs0, 2);
            rs1 += __shfl_xor_sync(0xffffffffu, rs1, 1);
            rs1 += __shfl_xor_sync(0xffffffffu, rs1, 2);
            ll[blk][0] = ll[blk][0] * al0 + rs0;
            ll[blk][1] = ll[blk][1] * al1 + rs1;
            #pragma unroll
            for (int j = 0; j < 8; j++) {
                O[blk][j][0] *= al0; O[blk][j][1] *= al0;
                O[blk][j][2] *= al1; O[blk][j][3] *= al1;
            }

            // ---- O += P V (3-term compensated) ----
            #pragma unroll
            for (int kb2 = 0; kb2 < 8; kb2++) {
                uint32_t ph[4], pl[4];
                split2(sacc[2*kb2][0],   sacc[2*kb2][1],   ph[0], pl[0]);
                split2(sacc[2*kb2][2],   sacc[2*kb2][3],   ph[1], pl[1]);
                split2(sacc[2*kb2+1][0], sacc[2*kb2+1][1], ph[2], pl[2]);
                split2(sacc[2*kb2+1][2], sacc[2*kb2+1][3], ph[3], pl[3]);
                #pragma unroll
                for (int nn = 0; nn < 4; nn++) {
                    uint32_t vhf[4], vlf[4];
                    uint32_t sw = SWZ((uint32_t)((kb2*16 + v_row) * 128 + (nn*16 + v_col) * 2));
                    ldsm4t(vhf, st + 32768 + sw);
                    ldsm4t(vlf, st + 49152 + sw);
                    mma16816(O[blk][2*nn],   ph, vhf[0], vhf[1]);
                    mma16816(O[blk][2*nn+1], ph, vhf[2], vhf[3]);
                    mma16816(O[blk][2*nn],   pl, vhf[0], vhf[1]);
                    mma16816(O[blk][2*nn+1], pl, vhf[2], vhf[3]);
                    mma16816(O[blk][2*nn],   ph, vlf[0], vlf[1]);
                    mma16816(O[blk][2*nn+1], ph, vlf[2], vlf[3]);
                }
            }
        }
    }

    // ---- epilogue: normalize, split hi/lo, write bf16 [t][h*64+hd] ----
    const int bb = bh >> 4;
    const int hh = bh & 15;
    #pragma unroll
    for (int blk = 0; blk < 2; blk++) {
        float r0 = 1.0f / ll[blk][0], r1 = 1.0f / ll[blk][1];
        const int t0 = bb * NL + q0 + wid*32 + blk*16 + g;
        #pragma unroll
        for (int j = 0; j < 8; j++) {
            int hd = hh*64 + j*8 + 2*t4;
            uint32_t hi, lo;
            split2(O[blk][j][0]*r0, O[blk][j][1]*r0, hi, lo);
            *(uint32_t*)&g_ah[(size_t)t0 * ND + hd] = hi;
            *(uint32_t*)&g_al[(size_t)t0 * ND + hd] = lo;
            split2(O[blk][j][2]*r1, O[blk][j][3]*r1, hi, lo);
            *(uint32_t*)&g_ah[(size_t)(t0 + 8) * ND + hd] = hi;
            *(uint32_t*)&g_al[(size_t)(t0 + 8) * ND + hd] = lo;
        }
    }
}

// ---------------- launch -----------------------------------------------------
extern "C" void kernel_launch(void* const* d_in, const int* in_sizes, int n_in,
                              void* d_out, int out_size) {
    const float* X  = (const float*)d_in[0];
    const float* Wq = (const float*)d_in[1];
    const float* bq = (const float*)d_in[2];
    const float* Wk = (const float*)d_in[3];
    const float* bk = (const float*)d_in[4];
    const float* Wv = (const float*)d_in[5];
    const float* bv = (const float*)d_in[6];
    const float* Wo = (const float*)d_in[7];
    const float* bo = (const float*)d_in[8];
    float* out = (float*)d_out;

    rope_tables_kernel<<<(NL*(NHD/2) + 255)/256, 256>>>();

    __nv_bfloat16 *xh, *xl;
    cudaGetSymbolAddress((void**)&xh, g_xh);
    cudaGetSymbolAddress((void**)&xl, g_xl);

    cvt_kernel<<<(NT*ND/4 + 255)/256, 256>>>(X, xh, xl, NT*ND/4);
    WPtrs wp; wp.p[0] = Wq; wp.p[1] = Wk; wp.p[2] = Wv; wp.p[3] = Wo;
    cvt_w_kernel<<<dim3((ND*ND/4 + 255)/256, 4), 256>>>(wp);

    cudaFuncSetAttribute(qkv_mma_kernel, cudaFuncAttributeMaxDynamicSharedMemorySize, GEMM_SMEM_BYTES);
    cudaFuncSetAttribute(out_mma_kernel, cudaFuncAttributeMaxDynamicSharedMemorySize, GEMM_SMEM_BYTES);
    cudaFuncSetAttribute(attn_mma_kernel, cudaFuncAttributeMaxDynamicSharedMemorySize, ATT_SMEM_BYTES);

    qkv_mma_kernel<<<dim3(ND/128, NT/128, 3), 256, GEMM_SMEM_BYTES>>>(bq, bk, bv);

    attn_mma_kernel<<<dim3(NL/256, NB*NH), 256, ATT_SMEM_BYTES>>>();

    out_mma_kernel<<<dim3(ND/128, NT/128), 256, GEMM_SMEM_BYTES>>>(bo, out);
}

// round 13
// speedup vs baseline: 1.0633x; 1.0633x over previous
#include <cuda_runtime.h>
#include <cuda_bf16.h>
#include <stdint.h>
#include <math.h>

#define NB 4
#define NL 2048
#define ND 1024
#define NH 16
#define NHD 64
#define NT (NB*NL)

// ---------------- scratch (device globals: no allocations allowed) ----------
__device__ __nv_bfloat16 g_xh[(size_t)NT*ND];
__device__ __nv_bfloat16 g_xl[(size_t)NT*ND];
__device__ __nv_bfloat16 g_wh[(size_t)4*ND*ND];   // Wq,Wk,Wv,Wo
__device__ __nv_bfloat16 g_wl[(size_t)4*ND*ND];
__device__ __nv_bfloat16 g_qh[(size_t)NB*NH*NL*NHD];  // [bh][l][hd]
__device__ __nv_bfloat16 g_ql[(size_t)NB*NH*NL*NHD];
__device__ __nv_bfloat16 g_kh[(size_t)NB*NH*NL*NHD];
__device__ __nv_bfloat16 g_kl[(size_t)NB*NH*NL*NHD];
__device__ __nv_bfloat16 g_vh[(size_t)NB*NH*NL*NHD];
__device__ __nv_bfloat16 g_vl[(size_t)NB*NH*NL*NHD];
__device__ __nv_bfloat16 g_ah[(size_t)NT*ND];     // attention out [t][h*64+hd]
__device__ __nv_bfloat16 g_al[(size_t)NT*ND];
__device__ float g_cos[NL*(NHD/2)];
__device__ float g_sin[NL*(NHD/2)];

// ---------------- helpers ----------------------------------------------------
__device__ __forceinline__ uint32_t smem_to_u32(const void* smem_ptr) {
    uint32_t addr;
    asm("{ .reg .u64 tmp; cvta.to.shared.u64 tmp, %1; cvt.u32.u64 %0, tmp; }"
        : "=r"(addr) : "l"(smem_ptr));
    return addr;
}
#define SWZ(off)   ((off) ^ (((off) >> 3) & 0x70))   // 128B rows
#define SWZ64(off) ((off) ^ (((off) >> 3) & 0x30))   // 64B rows

__device__ __forceinline__ void ldsm4(uint32_t* r, uint32_t a) {
    asm volatile("ldmatrix.sync.aligned.m8n8.x4.shared.b16 {%0,%1,%2,%3}, [%4];"
        : "=r"(r[0]), "=r"(r[1]), "=r"(r[2]), "=r"(r[3]) : "r"(a));
}
__device__ __forceinline__ void ldsm4t(uint32_t* r, uint32_t a) {
    asm volatile("ldmatrix.sync.aligned.m8n8.x4.trans.shared.b16 {%0,%1,%2,%3}, [%4];"
        : "=r"(r[0]), "=r"(r[1]), "=r"(r[2]), "=r"(r[3]) : "r"(a));
}
__device__ __forceinline__ void mma16816(float* c, const uint32_t* a,
                                         uint32_t b0, uint32_t b1) {
    asm volatile(
        "mma.sync.aligned.m16n8k16.row.col.f32.bf16.bf16.f32 "
        "{%0,%1,%2,%3}, {%4,%5,%6,%7}, {%8,%9}, {%0,%1,%2,%3};"
        : "+f"(c[0]), "+f"(c[1]), "+f"(c[2]), "+f"(c[3])
        : "r"(a[0]), "r"(a[1]), "r"(a[2]), "r"(a[3]), "r"(b0), "r"(b1));
}
__device__ __forceinline__ void split2(float a, float b, uint32_t& hi, uint32_t& lo) {
    __nv_bfloat162 h, l;
    h.x = __float2bfloat16(a); h.y = __float2bfloat16(b);
    l.x = __float2bfloat16(a - __bfloat162float(h.x));
    l.y = __float2bfloat16(b - __bfloat162float(h.y));
    hi = *(uint32_t*)&h; lo = *(uint32_t*)&l;
}
__device__ __forceinline__ void cp_async16(uint32_t sdst, const void* gsrc) {
    asm volatile("cp.async.cg.shared.global [%0], [%1], 16;"
        :: "r"(sdst), "l"(gsrc));
}
#define CP_COMMIT() asm volatile("cp.async.commit_group;" ::: "memory")
#define CP_WAIT(n)  asm volatile("cp.async.wait_group %0;" :: "n"(n) : "memory")

// [128 x 64] bf16 tile (row stride gstride elems) -> 128B-row swizzled smem
__device__ __forceinline__ void cp_tile(uint32_t sdst, const __nv_bfloat16* gsrc,
                                        int gstride, int tid) {
    #pragma unroll
    for (int it = 0; it < 4; it++) {
        int idx = tid + it * 256;          // 0..1023
        int row = idx >> 3, seg = idx & 7;
        cp_async16(sdst + SWZ((uint32_t)(row * 128 + seg * 16)),
                   gsrc + (size_t)row * gstride + seg * 8);
    }
}
// [128 x 32] bf16 tile -> 64B-row SW64 smem
__device__ __forceinline__ void cp_tile32(uint32_t sdst, const __nv_bfloat16* gsrc,
                                          int gstride, int tid) {
    #pragma unroll
    for (int it = 0; it < 2; it++) {
        int idx = tid + it * 256;          // 0..511
        int row = idx >> 2, seg = idx & 3;
        cp_async16(sdst + SWZ64((uint32_t)(row * 64 + seg * 16)),
                   gsrc + (size_t)row * gstride + seg * 8);
    }
}

// ---------------- K0a: RoPE tables (fp64 for accuracy) -----------------------
__global__ void rope_tables_kernel() {
    int idx = blockIdx.x * 256 + threadIdx.x;
    if (idx >= NL * (NHD/2)) return;
    int l = idx >> 5;
    int i = idx & 31;
    double inv = exp(-((double)(2*i) / (double)NHD) * log(10000.0));
    double a = (double)l * inv;
    g_cos[idx] = (float)cos(a);
    g_sin[idx] = (float)sin(a);
}

// ---------------- K0b: fp32 -> hi/lo bf16 converters -------------------------
__global__ void cvt_kernel(const float* __restrict__ src,
                           __nv_bfloat16* __restrict__ dh,
                           __nv_bfloat16* __restrict__ dl, int n4) {
    int i = blockIdx.x * 256 + threadIdx.x;
    if (i >= n4) return;
    float4 x = ((const float4*)src)[i];
    uint32_t h01, h23, l01, l23;
    split2(x.x, x.y, h01, l01);
    split2(x.z, x.w, h23, l23);
    ((uint2*)dh)[i] = make_uint2(h01, h23);
    ((uint2*)dl)[i] = make_uint2(l01, l23);
}
struct WPtrs { const float* p[4]; };
__global__ void cvt_w_kernel(WPtrs wp) {
    const int z = blockIdx.y;
    const float* src = wp.p[z];
    int i = blockIdx.x * 256 + threadIdx.x;
    if (i >= ND*ND/4) return;
    float4 x = ((const float4*)src)[i];
    uint32_t h01, h23, l01, l23;
    split2(x.x, x.y, h01, l01);
    split2(x.z, x.w, h23, l23);
    size_t base = (size_t)z * (ND*ND/4);
    ((uint2*)g_wh)[base + i] = make_uint2(h01, h23);
    ((uint2*)g_wl)[base + i] = make_uint2(l01, l23);
}

// ---------------- GEMM mainloop: K-chunk 32, 3-stage ring --------------------
// stage block 32KB: {AH:0, AL:8K, BH:16K, BL:24K}; stages at s%3 * 32768
#define GEMM_SMEM_BYTES (3*32768 + 1024)
#define NSTAGES_G (ND/32)      // 32

__device__ __forceinline__ void gemm_issue(
    uint32_t sb, int s, const __nv_bfloat16* Ah, const __nv_bfloat16* Al,
    const __nv_bfloat16* Bh, const __nv_bfloat16* Bl, int tid)
{
    uint32_t st = sb + (uint32_t)(s % 3) * 32768;
    int k0 = s * 32;
    cp_tile32(st + 0,     Ah + k0, ND, tid);
    cp_tile32(st + 8192,  Al + k0, ND, tid);
    cp_tile32(st + 16384, Bh + k0, ND, tid);
    cp_tile32(st + 24576, Bl + k0, ND, tid);
    CP_COMMIT();
}

__device__ __forceinline__ void gemm_mainloop_bf16(
    const __nv_bfloat16* __restrict__ Ah, const __nv_bfloat16* __restrict__ Al,
    const __nv_bfloat16* __restrict__ Bh, const __nv_bfloat16* __restrict__ Bl,
    uint32_t sb, float acc[2][8][4])
{
    const int tid = threadIdx.x;
    const int lid = tid & 31;
    const int wid = tid >> 5;
    const int wm = wid >> 1;
    const int wn = wid & 1;

    const int a_row = wm*32 + (lid & 7) + ((lid >> 3) & 1) * 8;
    const int a_cb  = (lid >> 4) * 8;
    const int b_row = wn*64 + (lid & 7) + ((lid >> 4) & 1) * 8;
    const int b_cb  = ((lid >> 3) & 1) * 8;

    gemm_issue(sb, 0, Ah, Al, Bh, Bl, tid);
    gemm_issue(sb, 1, Ah, Al, Bh, Bl, tid);
    for (int s = 0; s < NSTAGES_G; s++) {
        if (s + 2 < NSTAGES_G) { CP_WAIT(1); } else { CP_WAIT(0); }
        __syncthreads();     // reads of the buffer being refilled are retired
        if (s + 2 < NSTAGES_G)
            gemm_issue(sb, s + 2, Ah, Al, Bh, Bl, tid);
        uint32_t st = sb + (uint32_t)(s % 3) * 32768;

        #pragma unroll
        for (int ks = 0; ks < 2; ks++) {
            const int k0 = ks * 16;
            uint32_t ah[2][4], al[2][4], bh[4][4], bl[4][4];
            #pragma unroll
            for (int i = 0; i < 2; i++) {
                uint32_t sw = SWZ64((uint32_t)((a_row + i*16) * 64 + (k0 + a_cb) * 2));
                ldsm4(ah[i], st + 0 + sw);
                ldsm4(al[i], st + 8192 + sw);
            }
            #pragma unroll
            for (int jj = 0; jj < 4; jj++) {
                uint32_t sw = SWZ64((uint32_t)((b_row + jj*16) * 64 + (k0 + b_cb) * 2));
                ldsm4(bh[jj], st + 16384 + sw);
                ldsm4(bl[jj], st + 24576 + sw);
            }
            // term-major order: acc reuse distance 16 (no HMMA dependency stalls)
            #pragma unroll
            for (int i = 0; i < 2; i++)
                #pragma unroll
                for (int jj = 0; jj < 4; jj++) {
                    mma16816(acc[i][2*jj],   ah[i], bh[jj][0], bh[jj][1]);
                    mma16816(acc[i][2*jj+1], ah[i], bh[jj][2], bh[jj][3]);
                }
            #pragma unroll
            for (int i = 0; i < 2; i++)
                #pragma unroll
                for (int jj = 0; jj < 4; jj++) {
                    mma16816(acc[i][2*jj],   ah[i], bl[jj][0], bl[jj][1]);
                    mma16816(acc[i][2*jj+1], ah[i], bl[jj][2], bl[jj][3]);
                }
            #pragma unroll
            for (int i = 0; i < 2; i++)
                #pragma unroll
                for (int jj = 0; jj < 4; jj++) {
                    mma16816(acc[i][2*jj],   al[i], bh[jj][0], bh[jj][1]);
                    mma16816(acc[i][2*jj+1], al[i], bh[jj][2], bh[jj][3]);
                }
        }
    }
}

// ---------------- K1: fused QKV projection + RoPE ----------------------------
__global__ void __launch_bounds__(256, 2)
qkv_mma_kernel(const float* __restrict__ bq, const float* __restrict__ bk,
               const float* __restrict__ bv)
{
    extern __shared__ char dsm[];
    char* sbase = (char*)((((uintptr_t)dsm) + 1023) & ~(uintptr_t)1023);
    uint32_t sb = smem_to_u32(sbase);
    const int tid = threadIdx.x;
    const int lid = tid & 31;
    const int wid = tid >> 5;
    const int wm = wid >> 1;
    const int wn = wid & 1;

    const int z = blockIdx.z;
    const float* bias = (z == 0) ? bq : (z == 1) ? bk : bv;
    __nv_bfloat16* dsth = (z == 0) ? g_qh : (z == 1) ? g_kh : g_vh;
    __nv_bfloat16* dstl = (z == 0) ? g_ql : (z == 1) ? g_kl : g_vl;

    const int mBase = blockIdx.y * 128;
    const int nBase = blockIdx.x * 128;

    float acc[2][8][4] = {};
    gemm_mainloop_bf16(g_xh + (size_t)mBase * ND, g_xl + (size_t)mBase * ND,
                       g_wh + (size_t)z * ND * ND + (size_t)nBase * ND,
                       g_wl + (size_t)z * ND * ND + (size_t)nBase * ND,
                       sb, acc);

    const int g  = lid >> 2;
    const int t4 = lid & 3;
    #pragma unroll
    for (int i = 0; i < 2; i++) {
        #pragma unroll
        for (int rr = 0; rr < 2; rr++) {
            int t = mBase + wm*32 + i*16 + g + rr*8;
            int b = t >> 11;
            int l = t & (NL - 1);
            #pragma unroll
            for (int j = 0; j < 8; j++) {
                int c = nBase + wn*64 + j*8 + 2*t4;
                float y0 = acc[i][j][rr*2+0] + bias[c];
                float y1 = acc[i][j][rr*2+1] + bias[c+1];
                if (z < 2) {
                    int p0 = (c & 63) >> 1;
                    float co = g_cos[l*32 + p0], si = g_sin[l*32 + p0];
                    float e = y0, o = y1;
                    y0 = e*co - o*si;
                    y1 = e*si + o*co;
                }
                int h  = c >> 6;
                int hd = c & 63;
                size_t idx = (((size_t)(b*NH + h))*NL + l)*NHD + hd;
                uint32_t hi, lo;
                split2(y0, y1, hi, lo);
                *(uint32_t*)&dsth[idx] = hi;
                *(uint32_t*)&dstl[idx] = lo;
            }
        }
    }
}

// ---------------- K3: output projection --------------------------------------
__global__ void __launch_bounds__(256, 2)
out_mma_kernel(const float* __restrict__ bias, float* __restrict__ out)
{
    extern __shared__ char dsm[];
    char* sbase = (char*)((((uintptr_t)dsm) + 1023) & ~(uintptr_t)1023);
    uint32_t sb = smem_to_u32(sbase);
    const int tid = threadIdx.x;
    const int lid = tid & 31;
    const int wid = tid >> 5;
    const int wm = wid >> 1;
    const int wn = wid & 1;

    const int mBase = blockIdx.y * 128;
    const int nBase = blockIdx.x * 128;

    float acc[2][8][4] = {};
    gemm_mainloop_bf16(g_ah + (size_t)mBase * ND, g_al + (size_t)mBase * ND,
                       g_wh + (size_t)3 * ND * ND + (size_t)nBase * ND,
                       g_wl + (size_t)3 * ND * ND + (size_t)nBase * ND,
                       sb, acc);

    const int g  = lid >> 2;
    const int t4 = lid & 3;
    #pragma unroll
    for (int i = 0; i < 2; i++) {
        #pragma unroll
        for (int rr = 0; rr < 2; rr++) {
            int t = mBase + wm*32 + i*16 + g + rr*8;
            #pragma unroll
            for (int j = 0; j < 8; j++) {
                int c = nBase + wn*64 + j*8 + 2*t4;
                *(float2*)&out[(size_t)t * ND + c] = make_float2(
                    acc[i][j][rr*2+0] + bias[c],
                    acc[i][j][rr*2+1] + bias[c+1]);
            }
        }
    }
}

// ======================= K2: flash attention (bf16 + cp.async) ===============
// stage block 64KB: {KH:0, KL:16K, VH:32K, VL:48K}; stages at 0 / 65536
#define ATT_SMEM_BYTES (2*65536 + 1024)

__device__ __forceinline__ void attn_issue(uint32_t sb, int kt,
                                           const __nv_bfloat16* kh, const __nv_bfloat16* kl,
                                           const __nv_bfloat16* vh, const __nv_bfloat16* vl,
                                           int tid) {
    uint32_t st = sb + (uint32_t)(kt & 1) * 65536;
    size_t off = (size_t)kt * 128 * NHD;
    cp_tile(st + 0,     kh + off, NHD, tid);
    cp_tile(st + 16384, kl + off, NHD, tid);
    cp_tile(st + 32768, vh + off, NHD, tid);
    cp_tile(st + 49152, vl + off, NHD, tid);
    CP_COMMIT();
}

// grid (NL/128, NB*NH), 256 threads. CTA: 128 query rows of one (b,h).
// 8 warps, warp w owns query rows [w*16, w*16+16).
__global__ void __launch_bounds__(256, 1) attn_mma_kernel() {
    extern __shared__ char dsm[];
    char* sbase = (char*)((((uintptr_t)dsm) + 1023) & ~(uintptr_t)1023);
    uint32_t sb = smem_to_u32(sbase);

    const int tid = threadIdx.x;
    const int lid = tid & 31;
    const int wid = tid >> 5;
    const int bh = blockIdx.y;
    const int qt = (int)gridDim.x - 1 - (int)blockIdx.x;   // heavy tiles first
    const int q0 = qt * 128;

    const size_t hoff = (size_t)bh * (NL*NHD);
    const __nv_bfloat16* qh = g_qh + hoff;
    const __nv_bfloat16* ql = g_ql + hoff;
    const __nv_bfloat16* kh = g_kh + hoff;
    const __nv_bfloat16* kl = g_kl + hoff;
    const __nv_bfloat16* vh = g_vh + hoff;
    const __nv_bfloat16* vl = g_vl + hoff;

    // ---- load Q tile into stage-0 K buffers, pull fragments ----
    cp_tile(sb + 0,     qh + (size_t)q0 * NHD, NHD, tid);
    cp_tile(sb + 16384, ql + (size_t)q0 * NHD, NHD, tid);
    CP_COMMIT();
    CP_WAIT(0);
    __syncthreads();
    const int a_row = wid*16 + (lid & 7) + ((lid >> 3) & 1) * 8;
    const int a_cb  = (lid >> 4) * 8;
    uint32_t Qh[4][4], Ql[4][4];
    #pragma unroll
    for (int kb = 0; kb < 4; kb++) {
        uint32_t sw = SWZ((uint32_t)(a_row * 128 + (kb*16 + a_cb) * 2));
        ldsm4(Qh[kb], sb + 0 + sw);
        ldsm4(Ql[kb], sb + 16384 + sw);
    }
    __syncthreads();   // Q frags in regs; stage-0 buffers free for K/V

    const int g  = lid >> 2;
    const int t4 = lid & 3;
    float m0 = -1e30f, m1 = -1e30f, l0 = 0.f, l1 = 0.f;
    float O[8][4] = {};

    const int b_row = (lid & 7) + ((lid >> 4) & 1) * 8;
    const int b_cb  = ((lid >> 3) & 1) * 8;
    const int v_row = (lid & 7) + ((lid >> 3) & 1) * 8;
    const int v_col = ((lid >> 4) & 1) * 8;
    const int qrow0 = q0 + wid*16 + g;

    attn_issue(sb, 0, kh, kl, vh, vl, tid);
    for (int kt = 0; kt <= qt; kt++) {
        CP_WAIT(0);
        __syncthreads();    // reads of buffer (kt-1)&1 retired; safe to refill
        if (kt + 1 <= qt)
            attn_issue(sb, kt + 1, kh, kl, vh, vl, tid);
        uint32_t st = sb + (uint32_t)(kt & 1) * 65536;

        // ---- S = Q K^T (3-term compensated); jj processed in pairs ----
        float sacc[16][4] = {};
        #pragma unroll
        for (int kb = 0; kb < 4; kb++) {
            #pragma unroll
            for (int jp = 0; jp < 4; jp++) {
                uint32_t k0h[4], k0l[4], k1h[4], k1l[4];
                uint32_t sw0 = SWZ((uint32_t)(((2*jp)*16   + b_row) * 128 + (kb*16 + b_cb) * 2));
                uint32_t sw1 = SWZ((uint32_t)(((2*jp+1)*16 + b_row) * 128 + (kb*16 + b_cb) * 2));
                ldsm4(k0h, st + 0 + sw0);
                ldsm4(k1h, st + 0 + sw1);
                ldsm4(k0l, st + 16384 + sw0);
                ldsm4(k1l, st + 16384 + sw1);
                float* a0 = sacc[4*jp+0];
                float* a1 = sacc[4*jp+1];
                float* a2 = sacc[4*jp+2];
                float* a3 = sacc[4*jp+3];
                mma16816(a0, Qh[kb], k0h[0], k0h[1]);
                mma16816(a1, Qh[kb], k0h[2], k0h[3]);
                mma16816(a2, Qh[kb], k1h[0], k1h[1]);
                mma16816(a3, Qh[kb], k1h[2], k1h[3]);
                mma16816(a0, Ql[kb], k0h[0], k0h[1]);
                mma16816(a1, Ql[kb], k0h[2], k0h[3]);
                mma16816(a2, Ql[kb], k1h[0], k1h[1]);
                mma16816(a3, Ql[kb], k1h[2], k1h[3]);
                mma16816(a0, Qh[kb], k0l[0], k0l[1]);
                mma16816(a1, Qh[kb], k0l[2], k0l[3]);
                mma16816(a2, Qh[kb], k1l[0], k1l[1]);
                mma16816(a3, Qh[kb], k1l[2], k1l[3]);
            }
        }

        // ---- scale (+causal mask on the diagonal tile) ----
        const float scale = 0.125f;
        if (kt == qt) {
            #pragma unroll
            for (int j = 0; j < 16; j++) {
                int col = kt*128 + j*8 + 2*t4;
                #pragma unroll
                for (int e = 0; e < 4; e++) {
                    int c = col + (e & 1);
                    int r = qrow0 + (e >> 1) * 8;
                    sacc[j][e] = (c > r) ? -1e30f : sacc[j][e] * scale;
                }
            }
        } else {
            #pragma unroll
            for (int j = 0; j < 16; j++)
                #pragma unroll
                for (int e = 0; e < 4; e++) sacc[j][e] *= scale;
        }

        // ---- online softmax (quad-local reductions) ----
        float mx0 = -1e30f, mx1 = -1e30f;
        #pragma unroll
        for (int j = 0; j < 16; j++) {
            mx0 = fmaxf(mx0, fmaxf(sacc[j][0], sacc[j][1]));
            mx1 = fmaxf(mx1, fmaxf(sacc[j][2], sacc[j][3]));
        }
        mx0 = fmaxf(mx0, __shfl_xor_sync(0xffffffffu, mx0, 1));
        mx0 = fmaxf(mx0, __shfl_xor_sync(0xffffffffu, mx0, 2));
        mx1 = fmaxf(mx1, __shfl_xor_sync(0xffffffffu, mx1, 1));
        mx1 = fmaxf(mx1, __shfl_xor_sync(0xffffffffu, mx1, 2));

        float mn0 = fmaxf(m0, mx0), mn1 = fmaxf(m1, mx1);
        float al0 = __expf(m0 - mn0), al1 = __expf(m1 - mn1);
        m0 = mn0; m1 = mn1;

        float rs0 = 0.f, rs1 = 0.f;
        #pragma unroll
        for (int j = 0; j < 16; j++) {
            sacc[j][0] = __expf(sacc[j][0] - mn0);
            sacc[j][1] = __expf(sacc[j][1] - mn0);
            sacc[j][2] = __expf(sacc[j][2] - mn1);
            sacc[j][3] = __expf(sacc[j][3] - mn1);
            rs0 += sacc[j][0] + sacc[j][1];
            rs1 += sacc[j][2] + sacc[j][3];
        }
        rs0 += __shfl_xor_sync(0xffffffffu, rs0, 1);
        rs0 += __shfl_xor_sync(0xffffffffu, rs0, 2);
        rs1 += __shfl_xor_sync(0xffffffffu, rs1, 1);
        rs1 += __shfl_xor_sync(0xffffffffu, rs1, 2);
        l0 = l0 * al0 + rs0;
        l1 = l1 * al1 + rs1;
        #pragma unroll
        for (int j = 0; j < 8; j++) {
            O[j][0] *= al0; O[j][1] *= al0;
            O[j][2] *= al1; O[j][3] *= al1;
        }

        // ---- O += P V (3-term compensated); nn processed in pairs ----
        #pragma unroll
        for (int kb2 = 0; kb2 < 8; kb2++) {
            uint32_t ph[4], pl[4];
            split2(sacc[2*kb2][0],   sacc[2*kb2][1],   ph[0], pl[0]);
            split2(sacc[2*kb2][2],   sacc[2*kb2][3],   ph[1], pl[1]);
            split2(sacc[2*kb2+1][0], sacc[2*kb2+1][1], ph[2], pl[2]);
            split2(sacc[2*kb2+1][2], sacc[2*kb2+1][3], ph[3], pl[3]);
            #pragma unroll
            for (int np = 0; np < 2; np++) {
                uint32_t v0h[4], v0l[4], v1h[4], v1l[4];
                uint32_t sw0 = SWZ((uint32_t)((kb2*16 + v_row) * 128 + ((2*np)*16   + v_col) * 2));
                uint32_t sw1 = SWZ((uint32_t)((kb2*16 + v_row) * 128 + ((2*np+1)*16 + v_col) * 2));
                ldsm4t(v0h, st + 32768 + sw0);
                ldsm4t(v1h, st + 32768 + sw1);
                ldsm4t(v0l, st + 49152 + sw0);
                ldsm4t(v1l, st + 49152 + sw1);
                float* o0 = O[4*np+0];
                float* o1 = O[4*np+1];
                float* o2 = O[4*np+2];
                float* o3 = O[4*np+3];
                mma16816(o0, ph, v0h[0], v0h[1]);
                mma16816(o1, ph, v0h[2], v0h[3]);
                mma16816(o2, ph, v1h[0], v1h[1]);
                mma16816(o3, ph, v1h[2], v1h[3]);
                mma16816(o0, pl, v0h[0], v0h[1]);
                mma16816(o1, pl, v0h[2], v0h[3]);
                mma16816(o2, pl, v1h[0], v1h[1]);
                mma16816(o3, pl, v1h[2], v1h[3]);
                mma16816(o0, ph, v0l[0], v0l[1]);
                mma16816(o1, ph, v0l[2], v0l[3]);
                mma16816(o2, ph, v1l[0], v1l[1]);
                mma16816(o3, ph, v1l[2], v1l[3]);
            }
        }
    }

    // ---- epilogue: normalize, split hi/lo, write bf16 [t][h*64+hd] ----
    float r0 = 1.0f / l0, r1 = 1.0f / l1;
    const int bb = bh >> 4;
    const int hh = bh & 15;
    const int t0 = bb * NL + qrow0;
    #pragma unroll
    for (int j = 0; j < 8; j++) {
        int hd = hh*64 + j*8 + 2*t4;
        uint32_t hi, lo;
        split2(O[j][0]*r0, O[j][1]*r0, hi, lo);
        *(uint32_t*)&g_ah[(size_t)t0 * ND + hd] = hi;
        *(uint32_t*)&g_al[(size_t)t0 * ND + hd] = lo;
        split2(O[j][2]*r1, O[j][3]*r1, hi, lo);
        *(uint32_t*)&g_ah[(size_t)(t0 + 8) * ND + hd] = hi;
        *(uint32_t*)&g_al[(size_t)(t0 + 8) * ND + hd] = lo;
    }
}

// ---------------- launch -----------------------------------------------------
extern "C" void kernel_launch(void* const* d_in, const int* in_sizes, int n_in,
                              void* d_out, int out_size) {
    const float* X  = (const float*)d_in[0];
    const float* Wq = (const float*)d_in[1];
    const float* bq = (const float*)d_in[2];
    const float* Wk = (const float*)d_in[3];
    const float* bk = (const float*)d_in[4];
    const float* Wv = (const float*)d_in[5];
    const float* bv = (const float*)d_in[6];
    const float* Wo = (const float*)d_in[7];
    const float* bo = (const float*)d_in[8];
    float* out = (float*)d_out;

    rope_tables_kernel<<<(NL*(NHD/2) + 255)/256, 256>>>();

    __nv_bfloat16 *xh, *xl;
    cudaGetSymbolAddress((void**)&xh, g_xh);
    cudaGetSymbolAddress((void**)&xl, g_xl);

    cvt_kernel<<<(NT*ND/4 + 255)/256, 256>>>(X, xh, xl, NT*ND/4);
    WPtrs wp; wp.p[0] = Wq; wp.p[1] = Wk; wp.p[2] = Wv; wp.p[3] = Wo;
    cvt_w_kernel<<<dim3((ND*ND/4 + 255)/256, 4), 256>>>(wp);

    cudaFuncSetAttribute(qkv_mma_kernel, cudaFuncAttributeMaxDynamicSharedMemorySize, GEMM_SMEM_BYTES);
    cudaFuncSetAttribute(out_mma_kernel, cudaFuncAttributeMaxDynamicSharedMemorySize, GEMM_SMEM_BYTES);
    cudaFuncSetAttribute(attn_mma_kernel, cudaFuncAttributeMaxDynamicSharedMemorySize, ATT_SMEM_BYTES);

    qkv_mma_kernel<<<dim3(ND/128, NT/128, 3), 256, GEMM_SMEM_BYTES>>>(bq, bk, bv);

    attn_mma_kernel<<<dim3(NL/128, NB*NH), 256, ATT_SMEM_BYTES>>>();

    out_mma_kernel<<<dim3(ND/128, NT/128), 256, GEMM_SMEM_BYTES>>>(bo, out);
}

// round 14
// speedup vs baseline: 1.0969x; 1.0316x over previous
#include <cuda_runtime.h>
#include <cuda_bf16.h>
#include <stdint.h>
#include <math.h>

#define NB 4
#define NL 2048
#define ND 1024
#define NH 16
#define NHD 64
#define NT (NB*NL)

// ---------------- scratch (device globals: no allocations allowed) ----------
__device__ __nv_bfloat16 g_xh[(size_t)NT*ND];
__device__ __nv_bfloat16 g_xl[(size_t)NT*ND];
__device__ __nv_bfloat16 g_wh[(size_t)4*ND*ND];   // Wq,Wk,Wv,Wo
__device__ __nv_bfloat16 g_wl[(size_t)4*ND*ND];
__device__ __nv_bfloat16 g_qh[(size_t)NB*NH*NL*NHD];  // [bh][l][hd]
__device__ __nv_bfloat16 g_ql[(size_t)NB*NH*NL*NHD];
__device__ __nv_bfloat16 g_kh[(size_t)NB*NH*NL*NHD];
__device__ __nv_bfloat16 g_kl[(size_t)NB*NH*NL*NHD];
__device__ __nv_bfloat16 g_vh[(size_t)NB*NH*NL*NHD];
__device__ __nv_bfloat16 g_vl[(size_t)NB*NH*NL*NHD];
__device__ __nv_bfloat16 g_ah[(size_t)NT*ND];     // attention out [t][h*64+hd]
__device__ __nv_bfloat16 g_al[(size_t)NT*ND];
__device__ float g_cos[NL*(NHD/2)];
__device__ float g_sin[NL*(NHD/2)];

// ---------------- helpers ----------------------------------------------------
__device__ __forceinline__ uint32_t smem_to_u32(const void* smem_ptr) {
    uint32_t addr;
    asm("{ .reg .u64 tmp; cvta.to.shared.u64 tmp, %1; cvt.u32.u64 %0, tmp; }"
        : "=r"(addr) : "l"(smem_ptr));
    return addr;
}
#define SWZ(off)   ((off) ^ (((off) >> 3) & 0x70))   // 128B rows
#define SWZ64(off) ((off) ^ (((off) >> 3) & 0x30))   // 64B rows

__device__ __forceinline__ void ldsm4(uint32_t* r, uint32_t a) {
    asm volatile("ldmatrix.sync.aligned.m8n8.x4.shared.b16 {%0,%1,%2,%3}, [%4];"
        : "=r"(r[0]), "=r"(r[1]), "=r"(r[2]), "=r"(r[3]) : "r"(a));
}
__device__ __forceinline__ void ldsm4t(uint32_t* r, uint32_t a) {
    asm volatile("ldmatrix.sync.aligned.m8n8.x4.trans.shared.b16 {%0,%1,%2,%3}, [%4];"
        : "=r"(r[0]), "=r"(r[1]), "=r"(r[2]), "=r"(r[3]) : "r"(a));
}
__device__ __forceinline__ void mma16816(float* c, const uint32_t* a,
                                         uint32_t b0, uint32_t b1) {
    asm volatile(
        "mma.sync.aligned.m16n8k16.row.col.f32.bf16.bf16.f32 "
        "{%0,%1,%2,%3}, {%4,%5,%6,%7}, {%8,%9}, {%0,%1,%2,%3};"
        : "+f"(c[0]), "+f"(c[1]), "+f"(c[2]), "+f"(c[3])
        : "r"(a[0]), "r"(a[1]), "r"(a[2]), "r"(a[3]), "r"(b0), "r"(b1));
}
__device__ __forceinline__ void split2(float a, float b, uint32_t& hi, uint32_t& lo) {
    __nv_bfloat162 h, l;
    h.x = __float2bfloat16(a); h.y = __float2bfloat16(b);
    l.x = __float2bfloat16(a - __bfloat162float(h.x));
    l.y = __float2bfloat16(b - __bfloat162float(h.y));
    hi = *(uint32_t*)&h; lo = *(uint32_t*)&l;
}
__device__ __forceinline__ float ex2(float x) {
    float r;
    asm("ex2.approx.f32 %0, %1;" : "=f"(r) : "f"(x));
    return r;
}
__device__ __forceinline__ void cp_async16(uint32_t sdst, const void* gsrc) {
    asm volatile("cp.async.cg.shared.global [%0], [%1], 16;"
        :: "r"(sdst), "l"(gsrc));
}
#define CP_COMMIT() asm volatile("cp.async.commit_group;" ::: "memory")
#define CP_WAIT(n)  asm volatile("cp.async.wait_group %0;" :: "n"(n) : "memory")

// [128 x 64] bf16 tile (row stride gstride elems) -> 128B-row swizzled smem
__device__ __forceinline__ void cp_tile(uint32_t sdst, const __nv_bfloat16* gsrc,
                                        int gstride, int tid) {
    #pragma unroll
    for (int it = 0; it < 4; it++) {
        int idx = tid + it * 256;          // 0..1023
        int row = idx >> 3, seg = idx & 7;
        cp_async16(sdst + SWZ((uint32_t)(row * 128 + seg * 16)),
                   gsrc + (size_t)row * gstride + seg * 8);
    }
}
// [128 x 32] bf16 tile -> 64B-row SW64 smem
__device__ __forceinline__ void cp_tile32(uint32_t sdst, const __nv_bfloat16* gsrc,
                                          int gstride, int tid) {
    #pragma unroll
    for (int it = 0; it < 2; it++) {
        int idx = tid + it * 256;          // 0..511
        int row = idx >> 2, seg = idx & 3;
        cp_async16(sdst + SWZ64((uint32_t)(row * 64 + seg * 16)),
                   gsrc + (size_t)row * gstride + seg * 8);
    }
}

// ---------------- K0a: RoPE tables (fp64 for accuracy) -----------------------
__global__ void rope_tables_kernel() {
    int idx = blockIdx.x * 256 + threadIdx.x;
    if (idx >= NL * (NHD/2)) return;
    int l = idx >> 5;
    int i = idx & 31;
    double inv = exp(-((double)(2*i) / (double)NHD) * log(10000.0));
    double a = (double)l * inv;
    g_cos[idx] = (float)cos(a);
    g_sin[idx] = (float)sin(a);
}

// ---------------- K0b: fp32 -> hi/lo bf16 converters -------------------------
__global__ void cvt_kernel(const float* __restrict__ src,
                           __nv_bfloat16* __restrict__ dh,
                           __nv_bfloat16* __restrict__ dl, int n4) {
    int i = blockIdx.x * 256 + threadIdx.x;
    if (i >= n4) return;
    float4 x = ((const float4*)src)[i];
    uint32_t h01, h23, l01, l23;
    split2(x.x, x.y, h01, l01);
    split2(x.z, x.w, h23, l23);
    ((uint2*)dh)[i] = make_uint2(h01, h23);
    ((uint2*)dl)[i] = make_uint2(l01, l23);
}
struct WPtrs { const float* p[4]; };
__global__ void cvt_w_kernel(WPtrs wp) {
    const int z = blockIdx.y;
    const float* src = wp.p[z];
    int i = blockIdx.x * 256 + threadIdx.x;
    if (i >= ND*ND/4) return;
    float4 x = ((const float4*)src)[i];
    uint32_t h01, h23, l01, l23;
    split2(x.x, x.y, h01, l01);
    split2(x.z, x.w, h23, l23);
    size_t base = (size_t)z * (ND*ND/4);
    ((uint2*)g_wh)[base + i] = make_uint2(h01, h23);
    ((uint2*)g_wl)[base + i] = make_uint2(l01, l23);
}

// ---------------- GEMM mainloop: K-chunk 32, 2-stage, 1 barrier/stage --------
// stage block 32KB: {AH:0, AL:8K, BH:16K, BL:24K}; stages at 0 / 32768
#define GEMM_SMEM_BYTES (2*32768 + 1024)
#define NSTAGES_G (ND/32)      // 32

__device__ __forceinline__ void gemm_issue(
    uint32_t sb, int s, const __nv_bfloat16* Ah, const __nv_bfloat16* Al,
    const __nv_bfloat16* Bh, const __nv_bfloat16* Bl, int tid)
{
    uint32_t st = sb + (uint32_t)(s & 1) * 32768;
    int k0 = s * 32;
    cp_tile32(st + 0,     Ah + k0, ND, tid);
    cp_tile32(st + 8192,  Al + k0, ND, tid);
    cp_tile32(st + 16384, Bh + k0, ND, tid);
    cp_tile32(st + 24576, Bl + k0, ND, tid);
    CP_COMMIT();
}

__device__ __forceinline__ void gemm_mainloop_bf16(
    const __nv_bfloat16* __restrict__ Ah, const __nv_bfloat16* __restrict__ Al,
    const __nv_bfloat16* __restrict__ Bh, const __nv_bfloat16* __restrict__ Bl,
    uint32_t sb, float acc[2][8][4])
{
    const int tid = threadIdx.x;
    const int lid = tid & 31;
    const int wid = tid >> 5;
    const int wm = wid >> 1;
    const int wn = wid & 1;

    const int a_row = wm*32 + (lid & 7) + ((lid >> 3) & 1) * 8;
    const int a_cb  = (lid >> 4) * 8;
    const int b_row = wn*64 + (lid & 7) + ((lid >> 4) & 1) * 8;
    const int b_cb  = ((lid >> 3) & 1) * 8;

    gemm_issue(sb, 0, Ah, Al, Bh, Bl, tid);
    for (int s = 0; s < NSTAGES_G; s++) {
        CP_WAIT(0);
        __syncthreads();     // all reads of buffer (s-1)&1 retired; safe to refill
        if (s + 1 < NSTAGES_G)
            gemm_issue(sb, s + 1, Ah, Al, Bh, Bl, tid);
        uint32_t st = sb + (uint32_t)(s & 1) * 32768;

        #pragma unroll
        for (int ks = 0; ks < 2; ks++) {
            const int k0 = ks * 16;
            uint32_t ah[2][4], al[2][4], bh[4][4], bl[4][4];
            #pragma unroll
            for (int i = 0; i < 2; i++) {
                uint32_t sw = SWZ64((uint32_t)((a_row + i*16) * 64 + (k0 + a_cb) * 2));
                ldsm4(ah[i], st + 0 + sw);
                ldsm4(al[i], st + 8192 + sw);
            }
            #pragma unroll
            for (int jj = 0; jj < 4; jj++) {
                uint32_t sw = SWZ64((uint32_t)((b_row + jj*16) * 64 + (k0 + b_cb) * 2));
                ldsm4(bh[jj], st + 16384 + sw);
                ldsm4(bl[jj], st + 24576 + sw);
            }
            #pragma unroll
            for (int i = 0; i < 2; i++)
                #pragma unroll
                for (int jj = 0; jj < 4; jj++) {
                    mma16816(acc[i][2*jj],   ah[i], bh[jj][0], bh[jj][1]);
                    mma16816(acc[i][2*jj+1], ah[i], bh[jj][2], bh[jj][3]);
                    mma16816(acc[i][2*jj],   ah[i], bl[jj][0], bl[jj][1]);
                    mma16816(acc[i][2*jj+1], ah[i], bl[jj][2], bl[jj][3]);
                    mma16816(acc[i][2*jj],   al[i], bh[jj][0], bh[jj][1]);
                    mma16816(acc[i][2*jj+1], al[i], bh[jj][2], bh[jj][3]);
                }
        }
    }
}

// ---------------- K1: fused QKV projection + RoPE ----------------------------
__global__ void __launch_bounds__(256, 2)
qkv_mma_kernel(const float* __restrict__ bq, const float* __restrict__ bk,
               const float* __restrict__ bv)
{
    extern __shared__ char dsm[];
    char* sbase = (char*)((((uintptr_t)dsm) + 1023) & ~(uintptr_t)1023);
    uint32_t sb = smem_to_u32(sbase);
    const int tid = threadIdx.x;
    const int lid = tid & 31;
    const int wid = tid >> 5;
    const int wm = wid >> 1;
    const int wn = wid & 1;

    const int z = blockIdx.z;
    const float* bias = (z == 0) ? bq : (z == 1) ? bk : bv;
    __nv_bfloat16* dsth = (z == 0) ? g_qh : (z == 1) ? g_kh : g_vh;
    __nv_bfloat16* dstl = (z == 0) ? g_ql : (z == 1) ? g_kl : g_vl;

    const int mBase = blockIdx.y * 128;
    const int nBase = blockIdx.x * 128;

    float acc[2][8][4] = {};
    gemm_mainloop_bf16(g_xh + (size_t)mBase * ND, g_xl + (size_t)mBase * ND,
                       g_wh + (size_t)z * ND * ND + (size_t)nBase * ND,
                       g_wl + (size_t)z * ND * ND + (size_t)nBase * ND,
                       sb, acc);

    const int g  = lid >> 2;
    const int t4 = lid & 3;
    #pragma unroll
    for (int i = 0; i < 2; i++) {
        #pragma unroll
        for (int rr = 0; rr < 2; rr++) {
            int t = mBase + wm*32 + i*16 + g + rr*8;
            int b = t >> 11;
            int l = t & (NL - 1);
            #pragma unroll
            for (int j = 0; j < 8; j++) {
                int c = nBase + wn*64 + j*8 + 2*t4;
                float y0 = acc[i][j][rr*2+0] + bias[c];
                float y1 = acc[i][j][rr*2+1] + bias[c+1];
                if (z < 2) {
                    int p0 = (c & 63) >> 1;
                    float co = g_cos[l*32 + p0], si = g_sin[l*32 + p0];
                    float e = y0, o = y1;
                    y0 = e*co - o*si;
                    y1 = e*si + o*co;
                }
                int h  = c >> 6;
                int hd = c & 63;
                size_t idx = (((size_t)(b*NH + h))*NL + l)*NHD + hd;
                uint32_t hi, lo;
                split2(y0, y1, hi, lo);
                *(uint32_t*)&dsth[idx] = hi;
                *(uint32_t*)&dstl[idx] = lo;
            }
        }
    }
}

// ---------------- K3: output projection --------------------------------------
__global__ void __launch_bounds__(256, 2)
out_mma_kernel(const float* __restrict__ bias, float* __restrict__ out)
{
    extern __shared__ char dsm[];
    char* sbase = (char*)((((uintptr_t)dsm) + 1023) & ~(uintptr_t)1023);
    uint32_t sb = smem_to_u32(sbase);
    const int tid = threadIdx.x;
    const int lid = tid & 31;
    const int wid = tid >> 5;
    const int wm = wid >> 1;
    const int wn = wid & 1;

    const int mBase = blockIdx.y * 128;
    const int nBase = blockIdx.x * 128;

    float acc[2][8][4] = {};
    gemm_mainloop_bf16(g_ah + (size_t)mBase * ND, g_al + (size_t)mBase * ND,
                       g_wh + (size_t)3 * ND * ND + (size_t)nBase * ND,
                       g_wl + (size_t)3 * ND * ND + (size_t)nBase * ND,
                       sb, acc);

    const int g  = lid >> 2;
    const int t4 = lid & 3;
    #pragma unroll
    for (int i = 0; i < 2; i++) {
        #pragma unroll
        for (int rr = 0; rr < 2; rr++) {
            int t = mBase + wm*32 + i*16 + g + rr*8;
            #pragma unroll
            for (int j = 0; j < 8; j++) {
                int c = nBase + wn*64 + j*8 + 2*t4;
                *(float2*)&out[(size_t)t * ND + c] = make_float2(
                    acc[i][j][rr*2+0] + bias[c],
                    acc[i][j][rr*2+1] + bias[c+1]);
            }
        }
    }
}

// ======================= K2: flash attention (bf16 + cp.async) ===============
// stage block 64KB: {KH:0, KL:16K, VH:32K, VL:48K}; stages at 0 / 65536
#define ATT_SMEM_BYTES (2*65536 + 1024)

__device__ __forceinline__ void attn_issue(uint32_t sb, int kt,
                                           const __nv_bfloat16* kh, const __nv_bfloat16* kl,
                                           const __nv_bfloat16* vh, const __nv_bfloat16* vl,
                                           int tid) {
    uint32_t st = sb + (uint32_t)(kt & 1) * 65536;
    size_t off = (size_t)kt * 128 * NHD;
    cp_tile(st + 0,     kh + off, NHD, tid);
    cp_tile(st + 16384, kl + off, NHD, tid);
    cp_tile(st + 32768, vh + off, NHD, tid);
    cp_tile(st + 49152, vl + off, NHD, tid);
    CP_COMMIT();
}

// grid (NL/128, NB*NH), 256 threads. CTA: 128 query rows of one (b,h).
// 8 warps, warp w owns query rows [w*16, w*16+16).
// Softmax runs in base-2: S2 = S * 0.125 * log2(e); P = 2^(S2 - m2).
__global__ void __launch_bounds__(256, 1) attn_mma_kernel() {
    extern __shared__ char dsm[];
    char* sbase = (char*)((((uintptr_t)dsm) + 1023) & ~(uintptr_t)1023);
    uint32_t sb = smem_to_u32(sbase);

    const int tid = threadIdx.x;
    const int lid = tid & 31;
    const int wid = tid >> 5;
    const int bh = blockIdx.y;
    const int qt = (int)gridDim.x - 1 - (int)blockIdx.x;   // heavy tiles first
    const int q0 = qt * 128;

    const size_t hoff = (size_t)bh * (NL*NHD);
    const __nv_bfloat16* qh = g_qh + hoff;
    const __nv_bfloat16* ql = g_ql + hoff;
    const __nv_bfloat16* kh = g_kh + hoff;
    const __nv_bfloat16* kl = g_kl + hoff;
    const __nv_bfloat16* vh = g_vh + hoff;
    const __nv_bfloat16* vl = g_vl + hoff;

    // ---- load Q tile into stage-0 K buffers, pull fragments ----
    cp_tile(sb + 0,     qh + (size_t)q0 * NHD, NHD, tid);
    cp_tile(sb + 16384, ql + (size_t)q0 * NHD, NHD, tid);
    CP_COMMIT();
    CP_WAIT(0);
    __syncthreads();
    const int a_row = wid*16 + (lid & 7) + ((lid >> 3) & 1) * 8;
    const int a_cb  = (lid >> 4) * 8;
    uint32_t Qh[4][4], Ql[4][4];
    #pragma unroll
    for (int kb = 0; kb < 4; kb++) {
        uint32_t sw = SWZ((uint32_t)(a_row * 128 + (kb*16 + a_cb) * 2));
        ldsm4(Qh[kb], sb + 0 + sw);
        ldsm4(Ql[kb], sb + 16384 + sw);
    }
    __syncthreads();   // Q frags in regs; stage-0 buffers free for K/V

    const int g  = lid >> 2;
    const int t4 = lid & 3;
    float m0 = -1e30f, m1 = -1e30f, l0 = 0.f, l1 = 0.f;
    float O[8][4] = {};

    const int b_row = (lid & 7) + ((lid >> 4) & 1) * 8;
    const int b_cb  = ((lid >> 3) & 1) * 8;
    const int v_row = (lid & 7) + ((lid >> 3) & 1) * 8;
    const int v_col = ((lid >> 4) & 1) * 8;
    const int qrow0 = q0 + wid*16 + g;

    attn_issue(sb, 0, kh, kl, vh, vl, tid);
    for (int kt = 0; kt <= qt; kt++) {
        CP_WAIT(0);
        __syncthreads();    // reads of buffer (kt-1)&1 retired; safe to refill
        if (kt + 1 <= qt)
            attn_issue(sb, kt + 1, kh, kl, vh, vl, tid);
        uint32_t st = sb + (uint32_t)(kt & 1) * 65536;

        // ---- S = Q K^T (3-term compensated) ----
        float sacc[16][4] = {};
        #pragma unroll
        for (int kb = 0; kb < 4; kb++) {
            #pragma unroll
            for (int jj = 0; jj < 8; jj++) {
                uint32_t khf[4], klf[4];
                uint32_t sw = SWZ((uint32_t)((jj*16 + b_row) * 128 + (kb*16 + b_cb) * 2));
                ldsm4(khf, st + 0 + sw);
                ldsm4(klf, st + 16384 + sw);
                mma16816(sacc[2*jj],   Qh[kb], khf[0], khf[1]);
                mma16816(sacc[2*jj+1], Qh[kb], khf[2], khf[3]);
                mma16816(sacc[2*jj],   Ql[kb], khf[0], khf[1]);
                mma16816(sacc[2*jj+1], Ql[kb], khf[2], khf[3]);
                mma16816(sacc[2*jj],   Qh[kb], klf[0], klf[1]);
                mma16816(sacc[2*jj+1], Qh[kb], klf[2], klf[3]);
            }
        }

        // ---- scale into log2 domain (+causal mask on the diagonal tile) ----
        const float scale2 = 0.125f * 1.44269504088896340736f;   // /sqrt(64) * log2(e)
        if (kt == qt) {
            #pragma unroll
            for (int j = 0; j < 16; j++) {
                int col = kt*128 + j*8 + 2*t4;
                #pragma unroll
                for (int e = 0; e < 4; e++) {
                    int c = col + (e & 1);
                    int r = qrow0 + (e >> 1) * 8;
                    sacc[j][e] = (c > r) ? -1e30f : sacc[j][e] * scale2;
                }
            }
        } else {
            #pragma unroll
            for (int j = 0; j < 16; j++)
                #pragma unroll
                for (int e = 0; e < 4; e++) sacc[j][e] *= scale2;
        }

        // ---- online softmax in base-2 (quad-local reductions) ----
        float mx0 = -1e30f, mx1 = -1e30f;
        #pragma unroll
        for (int j = 0; j < 16; j++) {
            mx0 = fmaxf(mx0, fmaxf(sacc[j][0], sacc[j][1]));
            mx1 = fmaxf(mx1, fmaxf(sacc[j][2], sacc[j][3]));
        }
        mx0 = fmaxf(mx0, __shfl_xor_sync(0xffffffffu, mx0, 1));
        mx0 = fmaxf(mx0, __shfl_xor_sync(0xffffffffu, mx0, 2));
        mx1 = fmaxf(mx1, __shfl_xor_sync(0xffffffffu, mx1, 1));
        mx1 = fmaxf(mx1, __shfl_xor_sync(0xffffffffu, mx1, 2));

        float mn0 = fmaxf(m0, mx0), mn1 = fmaxf(m1, mx1);
        float al0 = ex2(m0 - mn0), al1 = ex2(m1 - mn1);
        m0 = mn0; m1 = mn1;

        float rs0 = 0.f, rs1 = 0.f;
        #pragma unroll
        for (int j = 0; j < 16; j++) {
            sacc[j][0] = ex2(sacc[j][0] - mn0);
            sacc[j][1] = ex2(sacc[j][1] - mn0);
            sacc[j][2] = ex2(sacc[j][2] - mn1);
            sacc[j][3] = ex2(sacc[j][3] - mn1);
            rs0 += sacc[j][0] + sacc[j][1];
            rs1 += sacc[j][2] + sacc[j][3];
        }
        rs0 += __shfl_xor_sync(0xffffffffu, rs0, 1);
        rs0 += __shfl_xor_sync(0xffffffffu, rs0, 2);
        rs1 += __shfl_xor_sync(0xffffffffu, rs1, 1);
        rs1 += __shfl_xor_sync(0xffffffffu, rs1, 2);
        l0 = l0 * al0 + rs0;
        l1 = l1 * al1 + rs1;
        #pragma unroll
        for (int j = 0; j < 8; j++) {
            O[j][0] *= al0; O[j][1] *= al0;
            O[j][2] *= al1; O[j][3] *= al1;
        }

        // ---- O += P V (3-term compensated; P frags straight from sacc) ----
        #pragma unroll
        for (int kb2 = 0; kb2 < 8; kb2++) {
            uint32_t ph[4], pl[4];
            split2(sacc[2*kb2][0],   sacc[2*kb2][1],   ph[0], pl[0]);
            split2(sacc[2*kb2][2],   sacc[2*kb2][3],   ph[1], pl[1]);
            split2(sacc[2*kb2+1][0], sacc[2*kb2+1][1], ph[2], pl[2]);
            split2(sacc[2*kb2+1][2], sacc[2*kb2+1][3], ph[3], pl[3]);
            #pragma unroll
            for (int nn = 0; nn < 4; nn++) {
                uint32_t vhf[4], vlf[4];
                uint32_t sw = SWZ((uint32_t)((kb2*16 + v_row) * 128 + (nn*16 + v_col) * 2));
                ldsm4t(vhf, st + 32768 + sw);
                ldsm4t(vlf, st + 49152 + sw);
                mma16816(O[2*nn],   ph, vhf[0], vhf[1]);
                mma16816(O[2*nn+1], ph, vhf[2], vhf[3]);
                mma16816(O[2*nn],   pl, vhf[0], vhf[1]);
                mma16816(O[2*nn+1], pl, vhf[2], vhf[3]);
                mma16816(O[2*nn],   ph, vlf[0], vlf[1]);
                mma16816(O[2*nn+1], ph, vlf[2], vlf[3]);
            }
        }
    }

    // ---- epilogue: normalize, split hi/lo, write bf16 [t][h*64+hd] ----
    float r0 = 1.0f / l0, r1 = 1.0f / l1;
    const int bb = bh >> 4;
    const int hh = bh & 15;
    const int t0 = bb * NL + qrow0;
    #pragma unroll
    for (int j = 0; j < 8; j++) {
        int hd = hh*64 + j*8 + 2*t4;
        uint32_t hi, lo;
        split2(O[j][0]*r0, O[j][1]*r0, hi, lo);
        *(uint32_t*)&g_ah[(size_t)t0 * ND + hd] = hi;
        *(uint32_t*)&g_al[(size_t)t0 * ND + hd] = lo;
        split2(O[j][2]*r1, O[j][3]*r1, hi, lo);
        *(uint32_t*)&g_ah[(size_t)(t0 + 8) * ND + hd] = hi;
        *(uint32_t*)&g_al[(size_t)(t0 + 8) * ND + hd] = lo;
    }
}

// ---------------- launch -----------------------------------------------------
extern "C" void kernel_launch(void* const* d_in, const int* in_sizes, int n_in,
                              void* d_out, int out_size) {
    const float* X  = (const float*)d_in[0];
    const float* Wq = (const float*)d_in[1];
    const float* bq = (const float*)d_in[2];
    const float* Wk = (const float*)d_in[3];
    const float* bk = (const float*)d_in[4];
    const float* Wv = (const float*)d_in[5];
    const float* bv = (const float*)d_in[6];
    const float* Wo = (const float*)d_in[7];
    const float* bo = (const float*)d_in[8];
    float* out = (float*)d_out;

    rope_tables_kernel<<<(NL*(NHD/2) + 255)/256, 256>>>();

    __nv_bfloat16 *xh, *xl;
    cudaGetSymbolAddress((void**)&xh, g_xh);
    cudaGetSymbolAddress((void**)&xl, g_xl);

    cvt_kernel<<<(NT*ND/4 + 255)/256, 256>>>(X, xh, xl, NT*ND/4);
    WPtrs wp; wp.p[0] = Wq; wp.p[1] = Wk; wp.p[2] = Wv; wp.p[3] = Wo;
    cvt_w_kernel<<<dim3((ND*ND/4 + 255)/256, 4), 256>>>(wp);

    cudaFuncSetAttribute(qkv_mma_kernel, cudaFuncAttributeMaxDynamicSharedMemorySize, GEMM_SMEM_BYTES);
    cudaFuncSetAttribute(out_mma_kernel, cudaFuncAttributeMaxDynamicSharedMemorySize, GEMM_SMEM_BYTES);
    cudaFuncSetAttribute(attn_mma_kernel, cudaFuncAttributeMaxDynamicSharedMemorySize, ATT_SMEM_BYTES);

    qkv_mma_kernel<<<dim3(ND/128, NT/128, 3), 256, GEMM_SMEM_BYTES>>>(bq, bk, bv);

    attn_mma_kernel<<<dim3(NL/128, NB*NH), 256, ATT_SMEM_BYTES>>>();

    out_mma_kernel<<<dim3(ND/128, NT/128), 256, GEMM_SMEM_BYTES>>>(bo, out);
}

// round 15
// speedup vs baseline: 1.4765x; 1.3461x over previous
#include <cuda_runtime.h>
#include <cuda_fp16.h>
#include <stdint.h>
#include <math.h>

#define NB 4
#define NL 2048
#define ND 1024
#define NH 16
#define NHD 64
#define NT (NB*NL)

// ---------------- scratch (device globals: no allocations allowed) ----------
// fp16 hi/lo split: lo kept only for A-side operands (2-term compensation)
__device__ __half g_xh[(size_t)NT*ND];
__device__ __half g_xl[(size_t)NT*ND];
__device__ __half g_wh[(size_t)4*ND*ND];              // Wq,Wk,Wv,Wo (hi only)
__device__ __half g_qh[(size_t)NB*NH*NL*NHD];         // [bh][l][hd]
__device__ __half g_ql[(size_t)NB*NH*NL*NHD];
__device__ __half g_kh[(size_t)NB*NH*NL*NHD];         // hi only
__device__ __half g_vh[(size_t)NB*NH*NL*NHD];         // hi only
__device__ __half g_ah[(size_t)NT*ND];                // attention out [t][h*64+hd]
__device__ __half g_al[(size_t)NT*ND];
__device__ float g_cos[NL*(NHD/2)];
__device__ float g_sin[NL*(NHD/2)];

// ---------------- helpers ----------------------------------------------------
__device__ __forceinline__ uint32_t smem_to_u32(const void* smem_ptr) {
    uint32_t addr;
    asm("{ .reg .u64 tmp; cvta.to.shared.u64 tmp, %1; cvt.u32.u64 %0, tmp; }"
        : "=r"(addr) : "l"(smem_ptr));
    return addr;
}
#define SWZ(off)   ((off) ^ (((off) >> 3) & 0x70))   // 128B rows
#define SWZ64(off) ((off) ^ (((off) >> 3) & 0x30))   // 64B rows

__device__ __forceinline__ void ldsm4(uint32_t* r, uint32_t a) {
    asm volatile("ldmatrix.sync.aligned.m8n8.x4.shared.b16 {%0,%1,%2,%3}, [%4];"
        : "=r"(r[0]), "=r"(r[1]), "=r"(r[2]), "=r"(r[3]) : "r"(a));
}
__device__ __forceinline__ void ldsm4t(uint32_t* r, uint32_t a) {
    asm volatile("ldmatrix.sync.aligned.m8n8.x4.trans.shared.b16 {%0,%1,%2,%3}, [%4];"
        : "=r"(r[0]), "=r"(r[1]), "=r"(r[2]), "=r"(r[3]) : "r"(a));
}
// fp16 MMA, fp32 accumulate
__device__ __forceinline__ void mma16816(float* c, const uint32_t* a,
                                         uint32_t b0, uint32_t b1) {
    asm volatile(
        "mma.sync.aligned.m16n8k16.row.col.f32.f16.f16.f32 "
        "{%0,%1,%2,%3}, {%4,%5,%6,%7}, {%8,%9}, {%0,%1,%2,%3};"
        : "+f"(c[0]), "+f"(c[1]), "+f"(c[2]), "+f"(c[3])
        : "r"(a[0]), "r"(a[1]), "r"(a[2]), "r"(a[3]), "r"(b0), "r"(b1));
}
// fp16 hi/lo split of a float pair, packed as half2
__device__ __forceinline__ void split2(float a, float b, uint32_t& hi, uint32_t& lo) {
    __half2 h, l;
    h.x = __float2half_rn(a); h.y = __float2half_rn(b);
    l.x = __float2half_rn(a - __half2float(h.x));
    l.y = __float2half_rn(b - __half2float(h.y));
    hi = *(uint32_t*)&h; lo = *(uint32_t*)&l;
}
// fp16 hi-only pack
__device__ __forceinline__ uint32_t pack2h(float a, float b) {
    __half2 h;
    h.x = __float2half_rn(a); h.y = __float2half_rn(b);
    return *(uint32_t*)&h;
}
__device__ __forceinline__ float ex2(float x) {
    float r;
    asm("ex2.approx.f32 %0, %1;" : "=f"(r) : "f"(x));
    return r;
}
__device__ __forceinline__ void cp_async16(uint32_t sdst, const void* gsrc) {
    asm volatile("cp.async.cg.shared.global [%0], [%1], 16;"
        :: "r"(sdst), "l"(gsrc));
}
#define CP_COMMIT() asm volatile("cp.async.commit_group;" ::: "memory")
#define CP_WAIT(n)  asm volatile("cp.async.wait_group %0;" :: "n"(n) : "memory")

// [128 x 64] fp16 tile (row stride gstride elems) -> 128B-row swizzled smem
__device__ __forceinline__ void cp_tile(uint32_t sdst, const __half* gsrc,
                                        int gstride, int tid) {
    #pragma unroll
    for (int it = 0; it < 4; it++) {
        int idx = tid + it * 256;          // 0..1023
        int row = idx >> 3, seg = idx & 7;
        cp_async16(sdst + SWZ((uint32_t)(row * 128 + seg * 16)),
                   gsrc + (size_t)row * gstride + seg * 8);
    }
}
// [128 x 32] fp16 tile -> 64B-row SW64 smem
__device__ __forceinline__ void cp_tile32(uint32_t sdst, const __half* gsrc,
                                          int gstride, int tid) {
    #pragma unroll
    for (int it = 0; it < 2; it++) {
        int idx = tid + it * 256;          // 0..511
        int row = idx >> 2, seg = idx & 3;
        cp_async16(sdst + SWZ64((uint32_t)(row * 64 + seg * 16)),
                   gsrc + (size_t)row * gstride + seg * 8);
    }
}

// ---------------- K0a: RoPE tables (fp64 for accuracy) -----------------------
__global__ void rope_tables_kernel() {
    int idx = blockIdx.x * 256 + threadIdx.x;
    if (idx >= NL * (NHD/2)) return;
    int l = idx >> 5;
    int i = idx & 31;
    double inv = exp(-((double)(2*i) / (double)NHD) * log(10000.0));
    double a = (double)l * inv;
    g_cos[idx] = (float)cos(a);
    g_sin[idx] = (float)sin(a);
}

// ---------------- K0b: fp32 -> fp16 converters -------------------------------
__global__ void cvt_kernel(const float* __restrict__ src,
                           __half* __restrict__ dh,
                           __half* __restrict__ dl, int n4) {
    int i = blockIdx.x * 256 + threadIdx.x;
    if (i >= n4) return;
    float4 x = ((const float4*)src)[i];
    uint32_t h01, h23, l01, l23;
    split2(x.x, x.y, h01, l01);
    split2(x.z, x.w, h23, l23);
    ((uint2*)dh)[i] = make_uint2(h01, h23);
    ((uint2*)dl)[i] = make_uint2(l01, l23);
}
struct WPtrs { const float* p[4]; };
__global__ void cvt_w_kernel(WPtrs wp) {
    const int z = blockIdx.y;
    const float* src = wp.p[z];
    int i = blockIdx.x * 256 + threadIdx.x;
    if (i >= ND*ND/4) return;
    float4 x = ((const float4*)src)[i];
    uint32_t h01 = pack2h(x.x, x.y);
    uint32_t h23 = pack2h(x.z, x.w);
    size_t base = (size_t)z * (ND*ND/4);
    ((uint2*)g_wh)[base + i] = make_uint2(h01, h23);
}

// ---------------- GEMM mainloop: K-chunk 32, 2-stage, fp16 2-term ------------
// stage block 24KB: {AH:0, AL:8K, BH:16K}; stages at 0 / 24576
#define GEMM_SMEM_BYTES (2*24576 + 1024)
#define NSTAGES_G (ND/32)      // 32

__device__ __forceinline__ void gemm_issue(
    uint32_t sb, int s, const __half* Ah, const __half* Al,
    const __half* Bh, int tid)
{
    uint32_t st = sb + (uint32_t)(s & 1) * 24576;
    int k0 = s * 32;
    cp_tile32(st + 0,     Ah + k0, ND, tid);
    cp_tile32(st + 8192,  Al + k0, ND, tid);
    cp_tile32(st + 16384, Bh + k0, ND, tid);
    CP_COMMIT();
}

__device__ __forceinline__ void gemm_mainloop_f16(
    const __half* __restrict__ Ah, const __half* __restrict__ Al,
    const __half* __restrict__ Bh, uint32_t sb, float acc[2][8][4])
{
    const int tid = threadIdx.x;
    const int lid = tid & 31;
    const int wid = tid >> 5;
    const int wm = wid >> 1;
    const int wn = wid & 1;

    const int a_row = wm*32 + (lid & 7) + ((lid >> 3) & 1) * 8;
    const int a_cb  = (lid >> 4) * 8;
    const int b_row = wn*64 + (lid & 7) + ((lid >> 4) & 1) * 8;
    const int b_cb  = ((lid >> 3) & 1) * 8;

    gemm_issue(sb, 0, Ah, Al, Bh, tid);
    for (int s = 0; s < NSTAGES_G; s++) {
        CP_WAIT(0);
        __syncthreads();     // all reads of the other buffer retired; safe to refill
        if (s + 1 < NSTAGES_G)
            gemm_issue(sb, s + 1, Ah, Al, Bh, tid);
        uint32_t st = sb + (uint32_t)(s & 1) * 24576;

        #pragma unroll
        for (int ks = 0; ks < 2; ks++) {
            const int k0 = ks * 16;
            uint32_t ah[2][4], al[2][4], bh[4][4];
            #pragma unroll
            for (int i = 0; i < 2; i++) {
                uint32_t sw = SWZ64((uint32_t)((a_row + i*16) * 64 + (k0 + a_cb) * 2));
                ldsm4(ah[i], st + 0 + sw);
                ldsm4(al[i], st + 8192 + sw);
            }
            #pragma unroll
            for (int jj = 0; jj < 4; jj++) {
                uint32_t sw = SWZ64((uint32_t)((b_row + jj*16) * 64 + (k0 + b_cb) * 2));
                ldsm4(bh[jj], st + 16384 + sw);
            }
            #pragma unroll
            for (int i = 0; i < 2; i++)
                #pragma unroll
                for (int jj = 0; jj < 4; jj++) {
                    mma16816(acc[i][2*jj],   ah[i], bh[jj][0], bh[jj][1]);
                    mma16816(acc[i][2*jj+1], ah[i], bh[jj][2], bh[jj][3]);
                    mma16816(acc[i][2*jj],   al[i], bh[jj][0], bh[jj][1]);
                    mma16816(acc[i][2*jj+1], al[i], bh[jj][2], bh[jj][3]);
                }
        }
    }
}

// ---------------- K1: fused QKV projection + RoPE ----------------------------
__global__ void __launch_bounds__(256, 2)
qkv_mma_kernel(const float* __restrict__ bq, const float* __restrict__ bk,
               const float* __restrict__ bv)
{
    extern __shared__ char dsm[];
    char* sbase = (char*)((((uintptr_t)dsm) + 1023) & ~(uintptr_t)1023);
    uint32_t sb = smem_to_u32(sbase);
    const int tid = threadIdx.x;
    const int lid = tid & 31;
    const int wid = tid >> 5;
    const int wm = wid >> 1;
    const int wn = wid & 1;

    const int z = blockIdx.z;
    const float* bias = (z == 0) ? bq : (z == 1) ? bk : bv;

    const int mBase = blockIdx.y * 128;
    const int nBase = blockIdx.x * 128;

    float acc[2][8][4] = {};
    gemm_mainloop_f16(g_xh + (size_t)mBase * ND, g_xl + (size_t)mBase * ND,
                      g_wh + (size_t)z * ND * ND + (size_t)nBase * ND,
                      sb, acc);

    const int g  = lid >> 2;
    const int t4 = lid & 3;
    #pragma unroll
    for (int i = 0; i < 2; i++) {
        #pragma unroll
        for (int rr = 0; rr < 2; rr++) {
            int t = mBase + wm*32 + i*16 + g + rr*8;
            int b = t >> 11;
            int l = t & (NL - 1);
            #pragma unroll
            for (int j = 0; j < 8; j++) {
                int c = nBase + wn*64 + j*8 + 2*t4;
                float y0 = acc[i][j][rr*2+0] + bias[c];
                float y1 = acc[i][j][rr*2+1] + bias[c+1];
                if (z < 2) {
                    int p0 = (c & 63) >> 1;
                    float co = g_cos[l*32 + p0], si = g_sin[l*32 + p0];
                    float e = y0, o = y1;
                    y0 = e*co - o*si;
                    y1 = e*si + o*co;
                }
                int h  = c >> 6;
                int hd = c & 63;
                size_t idx = (((size_t)(b*NH + h))*NL + l)*NHD + hd;
                if (z == 0) {
                    uint32_t hi, lo;
                    split2(y0, y1, hi, lo);
                    *(uint32_t*)&g_qh[idx] = hi;
                    *(uint32_t*)&g_ql[idx] = lo;
                } else if (z == 1) {
                    *(uint32_t*)&g_kh[idx] = pack2h(y0, y1);
                } else {
                    *(uint32_t*)&g_vh[idx] = pack2h(y0, y1);
                }
            }
        }
    }
}

// ---------------- K3: output projection --------------------------------------
__global__ void __launch_bounds__(256, 2)
out_mma_kernel(const float* __restrict__ bias, float* __restrict__ out)
{
    extern __shared__ char dsm[];
    char* sbase = (char*)((((uintptr_t)dsm) + 1023) & ~(uintptr_t)1023);
    uint32_t sb = smem_to_u32(sbase);
    const int tid = threadIdx.x;
    const int lid = tid & 31;
    const int wid = tid >> 5;
    const int wm = wid >> 1;
    const int wn = wid & 1;

    const int mBase = blockIdx.y * 128;
    const int nBase = blockIdx.x * 128;

    float acc[2][8][4] = {};
    gemm_mainloop_f16(g_ah + (size_t)mBase * ND, g_al + (size_t)mBase * ND,
                      g_wh + (size_t)3 * ND * ND + (size_t)nBase * ND,
                      sb, acc);

    const int g  = lid >> 2;
    const int t4 = lid & 3;
    #pragma unroll
    for (int i = 0; i < 2; i++) {
        #pragma unroll
        for (int rr = 0; rr < 2; rr++) {
            int t = mBase + wm*32 + i*16 + g + rr*8;
            #pragma unroll
            for (int j = 0; j < 8; j++) {
                int c = nBase + wn*64 + j*8 + 2*t4;
                *(float2*)&out[(size_t)t * ND + c] = make_float2(
                    acc[i][j][rr*2+0] + bias[c],
                    acc[i][j][rr*2+1] + bias[c+1]);
            }
        }
    }
}

// ======================= K2: flash attention (fp16 2-term) ===================
// stage block 32KB: {KH:0, VH:16K}; stages at 0 / 32768
#define ATT_SMEM_BYTES (2*32768 + 1024)

__device__ __forceinline__ void attn_issue(uint32_t sb, int kt,
                                           const __half* kh, const __half* vh,
                                           int tid) {
    uint32_t st = sb + (uint32_t)(kt & 1) * 32768;
    size_t off = (size_t)kt * 128 * NHD;
    cp_tile(st + 0,     kh + off, NHD, tid);
    cp_tile(st + 16384, vh + off, NHD, tid);
    CP_COMMIT();
}

// grid (NL/128, NB*NH), 256 threads. CTA: 128 query rows of one (b,h).
// Softmax runs in base-2.
__global__ void __launch_bounds__(256, 1) attn_mma_kernel() {
    extern __shared__ char dsm[];
    char* sbase = (char*)((((uintptr_t)dsm) + 1023) & ~(uintptr_t)1023);
    uint32_t sb = smem_to_u32(sbase);

    const int tid = threadIdx.x;
    const int lid = tid & 31;
    const int wid = tid >> 5;
    const int bh = blockIdx.y;
    const int qt = (int)gridDim.x - 1 - (int)blockIdx.x;   // heavy tiles first
    const int q0 = qt * 128;

    const size_t hoff = (size_t)bh * (NL*NHD);
    const __half* qh = g_qh + hoff;
    const __half* ql = g_ql + hoff;
    const __half* kh = g_kh + hoff;
    const __half* vh = g_vh + hoff;

    // ---- stage Q (hi->KH slot, lo->VH slot), pull fragments ----
    cp_tile(sb + 0,     qh + (size_t)q0 * NHD, NHD, tid);
    cp_tile(sb + 16384, ql + (size_t)q0 * NHD, NHD, tid);
    CP_COMMIT();
    CP_WAIT(0);
    __syncthreads();
    const int a_row = wid*16 + (lid & 7) + ((lid >> 3) & 1) * 8;
    const int a_cb  = (lid >> 4) * 8;
    uint32_t Qh[4][4], Ql[4][4];
    #pragma unroll
    for (int kb = 0; kb < 4; kb++) {
        uint32_t sw = SWZ((uint32_t)(a_row * 128 + (kb*16 + a_cb) * 2));
        ldsm4(Qh[kb], sb + 0 + sw);
        ldsm4(Ql[kb], sb + 16384 + sw);
    }
    __syncthreads();   // Q frags in regs; buffers free for K/V

    const int g  = lid >> 2;
    const int t4 = lid & 3;
    float m0 = -1e30f, m1 = -1e30f, l0 = 0.f, l1 = 0.f;
    float O[8][4] = {};

    const int b_row = (lid & 7) + ((lid >> 4) & 1) * 8;
    const int b_cb  = ((lid >> 3) & 1) * 8;
    const int v_row = (lid & 7) + ((lid >> 3) & 1) * 8;
    const int v_col = ((lid >> 4) & 1) * 8;
    const int qrow0 = q0 + wid*16 + g;

    attn_issue(sb, 0, kh, vh, tid);
    for (int kt = 0; kt <= qt; kt++) {
        CP_WAIT(0);
        __syncthreads();    // reads of buffer (kt-1)&1 retired; safe to refill
        if (kt + 1 <= qt)
            attn_issue(sb, kt + 1, kh, vh, tid);
        uint32_t st = sb + (uint32_t)(kt & 1) * 32768;

        // ---- S = Q K^T (2-term: QhKh + QlKh) ----
        float sacc[16][4] = {};
        #pragma unroll
        for (int kb = 0; kb < 4; kb++) {
            #pragma unroll
            for (int jj = 0; jj < 8; jj++) {
                uint32_t khf[4];
                uint32_t sw = SWZ((uint32_t)((jj*16 + b_row) * 128 + (kb*16 + b_cb) * 2));
                ldsm4(khf, st + 0 + sw);
                mma16816(sacc[2*jj],   Qh[kb], khf[0], khf[1]);
                mma16816(sacc[2*jj+1], Qh[kb], khf[2], khf[3]);
                mma16816(sacc[2*jj],   Ql[kb], khf[0], khf[1]);
                mma16816(sacc[2*jj+1], Ql[kb], khf[2], khf[3]);
            }
        }

        // ---- scale into log2 domain (+causal mask on the diagonal tile) ----
        const float scale2 = 0.125f * 1.44269504088896340736f;
        if (kt == qt) {
            #pragma unroll
            for (int j = 0; j < 16; j++) {
                int col = kt*128 + j*8 + 2*t4;
                #pragma unroll
                for (int e = 0; e < 4; e++) {
                    int c = col + (e & 1);
                    int r = qrow0 + (e >> 1) * 8;
                    sacc[j][e] = (c > r) ? -1e30f : sacc[j][e] * scale2;
                }
            }
        } else {
            #pragma unroll
            for (int j = 0; j < 16; j++)
                #pragma unroll
                for (int e = 0; e < 4; e++) sacc[j][e] *= scale2;
        }

        // ---- online softmax in base-2 (quad-local reductions) ----
        float mx0 = -1e30f, mx1 = -1e30f;
        #pragma unroll
        for (int j = 0; j < 16; j++) {
            mx0 = fmaxf(mx0, fmaxf(sacc[j][0], sacc[j][1]));
            mx1 = fmaxf(mx1, fmaxf(sacc[j][2], sacc[j][3]));
        }
        mx0 = fmaxf(mx0, __shfl_xor_sync(0xffffffffu, mx0, 1));
        mx0 = fmaxf(mx0, __shfl_xor_sync(0xffffffffu, mx0, 2));
        mx1 = fmaxf(mx1, __shfl_xor_sync(0xffffffffu, mx1, 1));
        mx1 = fmaxf(mx1, __shfl_xor_sync(0xffffffffu, mx1, 2));

        float mn0 = fmaxf(m0, mx0), mn1 = fmaxf(m1, mx1);
        float al0 = ex2(m0 - mn0), al1 = ex2(m1 - mn1);
        m0 = mn0; m1 = mn1;

        float rs0 = 0.f, rs1 = 0.f;
        #pragma unroll
        for (int j = 0; j < 16; j++) {
            sacc[j][0] = ex2(sacc[j][0] - mn0);
            sacc[j][1] = ex2(sacc[j][1] - mn0);
            sacc[j][2] = ex2(sacc[j][2] - mn1);
            sacc[j][3] = ex2(sacc[j][3] - mn1);
            rs0 += sacc[j][0] + sacc[j][1];
            rs1 += sacc[j][2] + sacc[j][3];
        }
        rs0 += __shfl_xor_sync(0xffffffffu, rs0, 1);
        rs0 += __shfl_xor_sync(0xffffffffu, rs0, 2);
        rs1 += __shfl_xor_sync(0xffffffffu, rs1, 1);
        rs1 += __shfl_xor_sync(0xffffffffu, rs1, 2);
        l0 = l0 * al0 + rs0;
        l1 = l1 * al1 + rs1;
        #pragma unroll
        for (int j = 0; j < 8; j++) {
            O[j][0] *= al0; O[j][1] *= al0;
            O[j][2] *= al1; O[j][3] *= al1;
        }

        // ---- O += P V (2-term: PhVh + PlVh) ----
        #pragma unroll
        for (int kb2 = 0; kb2 < 8; kb2++) {
            uint32_t ph[4], pl[4];
            split2(sacc[2*kb2][0],   sacc[2*kb2][1],   ph[0], pl[0]);
            split2(sacc[2*kb2][2],   sacc[2*kb2][3],   ph[1], pl[1]);
            split2(sacc[2*kb2+1][0], sacc[2*kb2+1][1], ph[2], pl[2]);
            split2(sacc[2*kb2+1][2], sacc[2*kb2+1][3], ph[3], pl[3]);
            #pragma unroll
            for (int nn = 0; nn < 4; nn++) {
                uint32_t vhf[4];
                uint32_t sw = SWZ((uint32_t)((kb2*16 + v_row) * 128 + (nn*16 + v_col) * 2));
                ldsm4t(vhf, st + 16384 + sw);
                mma16816(O[2*nn],   ph, vhf[0], vhf[1]);
                mma16816(O[2*nn+1], ph, vhf[2], vhf[3]);
                mma16816(O[2*nn],   pl, vhf[0], vhf[1]);
                mma16816(O[2*nn+1], pl, vhf[2], vhf[3]);
            }
        }
    }

    // ---- epilogue: normalize, split hi/lo, write fp16 [t][h*64+hd] ----
    float r0 = 1.0f / l0, r1 = 1.0f / l1;
    const int bb = bh >> 4;
    const int hh = bh & 15;
    const int t0 = bb * NL + qrow0;
    #pragma unroll
    for (int j = 0; j < 8; j++) {
        int hd = hh*64 + j*8 + 2*t4;
        uint32_t hi, lo;
        split2(O[j][0]*r0, O[j][1]*r0, hi, lo);
        *(uint32_t*)&g_ah[(size_t)t0 * ND + hd] = hi;
        *(uint32_t*)&g_al[(size_t)t0 * ND + hd] = lo;
        split2(O[j][2]*r1, O[j][3]*r1, hi, lo);
        *(uint32_t*)&g_ah[(size_t)(t0 + 8) * ND + hd] = hi;
        *(uint32_t*)&g_al[(size_t)(t0 + 8) * ND + hd] = lo;
    }
}

// ---------------- launch -----------------------------------------------------
extern "C" void kernel_launch(void* const* d_in, const int* in_sizes, int n_in,
                              void* d_out, int out_size) {
    const float* X  = (const float*)d_in[0];
    const float* Wq = (const float*)d_in[1];
    const float* bq = (const float*)d_in[2];
    const float* Wk = (const float*)d_in[3];
    const float* bk = (const float*)d_in[4];
    const float* Wv = (const float*)d_in[5];
    const float* bv = (const float*)d_in[6];
    const float* Wo = (const float*)d_in[7];
    const float* bo = (const float*)d_in[8];
    float* out = (float*)d_out;

    rope_tables_kernel<<<(NL*(NHD/2) + 255)/256, 256>>>();

    __half *xh, *xl;
    cudaGetSymbolAddress((void**)&xh, g_xh);
    cudaGetSymbolAddress((void**)&xl, g_xl);

    cvt_kernel<<<(NT*ND/4 + 255)/256, 256>>>(X, xh, xl, NT*ND/4);
    WPtrs wp; wp.p[0] = Wq; wp.p[1] = Wk; wp.p[2] = Wv; wp.p[3] = Wo;
    cvt_w_kernel<<<dim3((ND*ND/4 + 255)/256, 4), 256>>>(wp);

    cudaFuncSetAttribute(qkv_mma_kernel, cudaFuncAttributeMaxDynamicSharedMemorySize, GEMM_SMEM_BYTES);
    cudaFuncSetAttribute(out_mma_kernel, cudaFuncAttributeMaxDynamicSharedMemorySize, GEMM_SMEM_BYTES);
    cudaFuncSetAttribute(attn_mma_kernel, cudaFuncAttributeMaxDynamicSharedMemorySize, ATT_SMEM_BYTES);

    qkv_mma_kernel<<<dim3(ND/128, NT/128, 3), 256, GEMM_SMEM_BYTES>>>(bq, bk, bv);

    attn_mma_kernel<<<dim3(NL/128, NB*NH), 256, ATT_SMEM_BYTES>>>();

    out_mma_kernel<<<dim3(ND/128, NT/128), 256, GEMM_SMEM_BYTES>>>(bo, out);
}